// round 1
// baseline (speedup 1.0000x reference)
#include <cuda_runtime.h>

// ---------------- scratch (device globals; no allocations) ----------------
__device__ float g_x   [18874368];   // [16][64][18432] patch-major im2col of s1
__device__ float g_z   [18874368];   // conv+bn+relu+mask output
__device__ float g_ori [2097152];    // [16][1024][128] pooled short tokens
__device__ float g_sn  [2097152];    // LN(ori)
__device__ float g_ofr [2097152];    // pooled o tokens (raw)
__device__ float g_of  [2097152];    // LN(of)
__device__ float g_q   [2097152];    // [16][4][1024][32]
__device__ float g_k   [2097152];
__device__ float g_v   [2097152];
__device__ float g_yv  [2097152];
__device__ float g_xv  [2097152];    // [16][1024][128]
__device__ float g_x2  [2097152];    // [16][128][1024]
__device__ float g_y2  [2097152];    // conv1d output
__device__ float g_wpe [20480];      // [5][64pi][64po]
__device__ float g_wc1 [81920];      // [5][128ci][128co]

// ---------------- weight repack (k-major -> coalescable) -------------------
__global__ void k_repack(const float* __restrict__ pe_w, const float* __restrict__ c1d_w) {
    int idx = blockIdx.x * 256 + threadIdx.x;
    if (idx < 20480) {
        int k = idx / 4096, r = idx % 4096, pi = r / 64, po = r % 64;
        g_wpe[idx] = pe_w[(po * 64 + pi) * 5 + k];
    }
    if (idx < 81920) {
        int k = idx / 16384, r = idx % 16384, ci = r / 128, co = r % 128;
        g_wc1[idx] = c1d_w[(co * 128 + ci) * 5 + k];
    }
}

// ---------------- s1 -> patch-major layout (smem transpose) ----------------
// g_x[b][pi][f], pi=h*8+w, f=(p1*12+p2)*128+c
__global__ void k_transpose(const float* __restrict__ s1) {
    __shared__ float t[32][33];
    int b = blockIdx.z >> 2, cg = blockIdx.z & 3;
    int row = blockIdx.y;               // 0..95  = h*12+p1
    int W0 = blockIdx.x * 32;
    int tx = threadIdx.x, ty = threadIdx.y;
    t[ty][tx] = s1[((b * 128 + cg * 32 + ty) * 96 + row) * 96 + W0 + tx];
    __syncthreads();
    int Wl = W0 + ty;
    int w = Wl / 12, p2 = Wl % 12;
    int h = row / 12, p1 = row % 12;
    g_x[(b * 64 + h * 8 + w) * 18432 + (p1 * 12 + p2) * 128 + cg * 32 + tx] = t[tx][ty];
}

// ---------------- patch-embed conv (5 shifted 64x64 GEMMs) + BN + ReLU + mask
#define TILE_F 96
__global__ __launch_bounds__(256) void k_peconv(
    const int* __restrict__ index,
    const float* __restrict__ bn_g, const float* __restrict__ bn_b,
    const float* __restrict__ bn_m, const float* __restrict__ bn_v) {
    __shared__ float Xs[64 * 100];      // 64 pi x (96+4) f
    __shared__ float Ws[64 * 64];       // [pi][po]
    int b = blockIdx.y;
    int f0 = blockIdx.x * TILE_F;
    int tx = threadIdx.x, ty = threadIdx.y;
    int tid = ty * 32 + tx;

    for (int idx = tid; idx < 6400; idx += 256) {
        int pi = idx / 100, t = idx % 100;
        int f = f0 - 2 + t;
        Xs[idx] = (f >= 0 && f < 18432) ? g_x[(b * 64 + pi) * 18432 + f] : 0.f;
    }

    float acc[8][3];
#pragma unroll
    for (int i = 0; i < 8; i++)
#pragma unroll
        for (int j = 0; j < 3; j++) acc[i][j] = 0.f;

    for (int k = 0; k < 5; k++) {
        __syncthreads();
        for (int idx = tid; idx < 4096; idx += 256) Ws[idx] = g_wpe[k * 4096 + idx];
        __syncthreads();
#pragma unroll 4
        for (int pi = 0; pi < 64; pi++) {
            float4 w0 = *(const float4*)&Ws[pi * 64 + ty * 8];
            float4 w1 = *(const float4*)&Ws[pi * 64 + ty * 8 + 4];
            float w[8] = {w0.x, w0.y, w0.z, w0.w, w1.x, w1.y, w1.z, w1.w};
            float x0 = Xs[pi * 100 + tx + k];
            float x1 = Xs[pi * 100 + tx + 32 + k];
            float x2 = Xs[pi * 100 + tx + 64 + k];
#pragma unroll
            for (int i = 0; i < 8; i++) {
                acc[i][0] += w[i] * x0;
                acc[i][1] += w[i] * x1;
                acc[i][2] += w[i] * x2;
            }
        }
    }

    int pidx0 = (index[0] / 12) * 8 + index[1] / 12;
    int pidx1 = (index[2] / 12) * 8 + index[3] / 12;
    int pidx2 = (index[4] / 12) * 8 + index[5] / 12;
    int pidx3 = (index[6] / 12) * 8 + index[7] / 12;

#pragma unroll
    for (int i = 0; i < 8; i++) {
        int po = ty * 8 + i;
        bool sel = (po == pidx0) | (po == pidx1) | (po == pidx2) | (po == pidx3);
        float mm = bn_m[po];
        float invs = rsqrtf(bn_v[po] + 1e-5f);
        float gg = bn_g[po], bb = bn_b[po];
#pragma unroll
        for (int j = 0; j < 3; j++) {
            float v = (acc[i][j] - mm) * invs * gg + bb;
            v = fmaxf(v, 0.f);
            if (!sel) v *= v;
            g_z[(b * 64 + po) * 18432 + f0 + tx + 32 * j] = v;
        }
    }
}

// ---------------- LN helper (blockDim.x == 128) ----------------------------
__device__ __forceinline__ void ln_stats128(float v, float& mean, float& rstd) {
    float s = v, s2 = v * v;
#pragma unroll
    for (int off = 16; off; off >>= 1) {
        s  += __shfl_xor_sync(0xffffffffu, s,  off);
        s2 += __shfl_xor_sync(0xffffffffu, s2, off);
    }
    __shared__ float sm[4], sm2[4];
    int w = threadIdx.x >> 5, ln = threadIdx.x & 31;
    if (ln == 0) { sm[w] = s; sm2[w] = s2; }
    __syncthreads();
    s  = sm[0] + sm[1] + sm[2] + sm[3];
    s2 = sm2[0] + sm2[1] + sm2[2] + sm2[3];
    mean = s * (1.f / 128.f);
    float var = s2 * (1.f / 128.f) - mean * mean;
    rstd = rsqrtf(var + 1e-5f);
}

// ---------------- 3x3 pool of z -> ori tokens + LN -> sn -------------------
__global__ void k_pool_short(const float* __restrict__ lny_g, const float* __restrict__ lny_b) {
    int n = blockIdx.x, b = blockIdx.y, c = threadIdx.x;
    int oh = n >> 5, ow = n & 31;
    int p = (oh >> 2) * 8 + (ow >> 2);
    int base = (b * 64 + p) * 18432;
    int p1s = (oh & 3) * 3, p2s = (ow & 3) * 3;
    float s = 0.f;
#pragma unroll
    for (int r = 0; r < 3; r++)
#pragma unroll
        for (int t = 0; t < 3; t++)
            s += g_z[base + ((p1s + r) * 12 + p2s + t) * 128 + c];
    s *= (1.f / 9.f);
    g_ori[(b * 1024 + n) * 128 + c] = s;
    float mean, rstd;
    ln_stats128(s, mean, rstd);
    g_sn[(b * 1024 + n) * 128 + c] = (s - mean) * rstd * lny_g[c] + lny_b[c];
}

// ---------------- 2x2 pool of o, transposed to token-major -----------------
__global__ void k_pool_o(const float* __restrict__ o) {
    __shared__ float T[32][33];
    int oh = blockIdx.x, cg = blockIdx.y, b = blockIdx.z;
    int tid = threadIdx.x;
#pragma unroll
    for (int it = 0; it < 4; it++) {
        int idx = it * 256 + tid;
        int cl = idx >> 5, ow = idx & 31;
        const float* p = &o[((b * 128 + cg * 32 + cl) * 64 + 2 * oh) * 64 + 2 * ow];
        T[cl][ow] = 0.25f * (p[0] + p[1] + p[64] + p[65]);
    }
    __syncthreads();
#pragma unroll
    for (int it = 0; it < 4; it++) {
        int idx = it * 256 + tid;
        int cl = idx & 31, ow = idx >> 5;
        g_ofr[(b * 1024 + oh * 32 + ow) * 128 + cg * 32 + cl] = T[cl][ow];
    }
}

__global__ void k_ln_of(const float* __restrict__ lnx_g, const float* __restrict__ lnx_b) {
    int n = blockIdx.x, b = blockIdx.y, c = threadIdx.x;
    float v = g_ofr[(b * 1024 + n) * 128 + c];
    float mean, rstd;
    ln_stats128(v, mean, rstd);
    g_of[(b * 1024 + n) * 128 + c] = (v - mean) * rstd * lnx_g[c] + lnx_b[c];
}

// ---------------- QKV projection: [1024x128] @ [128x384]^T -----------------
__global__ __launch_bounds__(256) void k_qkv(const float* __restrict__ qkv_w, const float* __restrict__ qkv_b) {
    __shared__ float As[64 * 65], Bs[64 * 65];
    int b = blockIdx.z;
    int n0 = blockIdx.x * 64, j0 = blockIdx.y * 64;
    int tx = threadIdx.x, ty = threadIdx.y, tid = ty * 16 + tx;
    float acc[4][4] = {};
    for (int kc = 0; kc < 2; kc++) {
        __syncthreads();
        for (int idx = tid; idx < 4096; idx += 256) {
            int r = idx >> 6, kk = idx & 63;
            As[r * 65 + kk] = g_of[(b * 1024 + n0 + r) * 128 + kc * 64 + kk];
            Bs[r * 65 + kk] = qkv_w[(j0 + r) * 128 + kc * 64 + kk];
        }
        __syncthreads();
#pragma unroll 8
        for (int kk = 0; kk < 64; kk++) {
            float a[4], w[4];
#pragma unroll
            for (int i = 0; i < 4; i++) a[i] = As[(i * 16 + tx) * 65 + kk];
#pragma unroll
            for (int j = 0; j < 4; j++) w[j] = Bs[(j * 16 + ty) * 65 + kk];
#pragma unroll
            for (int i = 0; i < 4; i++)
#pragma unroll
                for (int j = 0; j < 4; j++) acc[i][j] += a[i] * w[j];
        }
    }
#pragma unroll
    for (int i = 0; i < 4; i++)
#pragma unroll
        for (int j = 0; j < 4; j++) {
            int n = n0 + i * 16 + tx;
            int jj = j0 + j * 16 + ty;
            float v = acc[i][j] + qkv_b[jj];
            int which = jj >> 7, rem = jj & 127, h = rem >> 5, d = rem & 31;
            float* dst = which == 0 ? g_q : (which == 1 ? g_k : g_v);
            dst[((b * 4 + h) * 1024 + n) * 32 + d] = v;
        }
}

// ---------------- YV projection --------------------------------------------
__global__ __launch_bounds__(256) void k_yvp(const float* __restrict__ yv_w, const float* __restrict__ yv_b) {
    __shared__ float As[64 * 65], Bs[64 * 65];
    int b = blockIdx.z;
    int n0 = blockIdx.x * 64, j0 = blockIdx.y * 64;
    int tx = threadIdx.x, ty = threadIdx.y, tid = ty * 16 + tx;
    float acc[4][4] = {};
    for (int kc = 0; kc < 2; kc++) {
        __syncthreads();
        for (int idx = tid; idx < 4096; idx += 256) {
            int r = idx >> 6, kk = idx & 63;
            As[r * 65 + kk] = g_sn[(b * 1024 + n0 + r) * 128 + kc * 64 + kk];
            Bs[r * 65 + kk] = yv_w[(j0 + r) * 128 + kc * 64 + kk];
        }
        __syncthreads();
#pragma unroll 8
        for (int kk = 0; kk < 64; kk++) {
            float a[4], w[4];
#pragma unroll
            for (int i = 0; i < 4; i++) a[i] = As[(i * 16 + tx) * 65 + kk];
#pragma unroll
            for (int j = 0; j < 4; j++) w[j] = Bs[(j * 16 + ty) * 65 + kk];
#pragma unroll
            for (int i = 0; i < 4; i++)
#pragma unroll
                for (int j = 0; j < 4; j++) acc[i][j] += a[i] * w[j];
        }
    }
#pragma unroll
    for (int i = 0; i < 4; i++)
#pragma unroll
        for (int j = 0; j < 4; j++) {
            int n = n0 + i * 16 + tx;
            int jj = j0 + j * 16 + ty;
            int h = jj >> 5, d = jj & 31;
            g_yv[((b * 4 + h) * 1024 + n) * 32 + d] = acc[i][j] + yv_b[jj];
        }
}

// ---------------- flash attention: per (bh, 64-row tile) -------------------
__global__ __launch_bounds__(256) void k_attn() {
    __shared__ float Qs[64 * 33], Ks[64 * 33], Vs[64 * 33], Ss[64 * 65];
    int bh = blockIdx.y;
    int n0 = blockIdx.x * 64;
    int b = bh >> 2, h = bh & 3;
    int tx = threadIdx.x, ty = threadIdx.y, tid = ty * 16 + tx;

    for (int idx = tid; idx < 2048; idx += 256) {
        int r = idx >> 5, d = idx & 31;
        Qs[r * 33 + d] = g_q[(bh * 1024 + n0 + r) * 32 + d];
    }

    float m[4], l[4] = {0, 0, 0, 0}, O[4][2] = {};
#pragma unroll
    for (int ri = 0; ri < 4; ri++) m[ri] = -1e30f;
    const float sc = 0.17677669529663687f;   // 1/sqrt(32)

    for (int ct = 0; ct < 16; ct++) {
        __syncthreads();
        for (int idx = tid; idx < 2048; idx += 256) {
            int r = idx >> 5, d = idx & 31;
            Ks[r * 33 + d] = g_k [(bh * 1024 + ct * 64 + r) * 32 + d];
            Vs[r * 33 + d] = g_yv[(bh * 1024 + ct * 64 + r) * 32 + d];
        }
        __syncthreads();
        float s[4][4] = {};
#pragma unroll 8
        for (int d = 0; d < 32; d++) {
            float a[4], kv[4];
#pragma unroll
            for (int ri = 0; ri < 4; ri++) a[ri]  = Qs[(ty * 4 + ri) * 33 + d];
#pragma unroll
            for (int ci = 0; ci < 4; ci++) kv[ci] = Ks[(tx * 4 + ci) * 33 + d];
#pragma unroll
            for (int ri = 0; ri < 4; ri++)
#pragma unroll
                for (int ci = 0; ci < 4; ci++) s[ri][ci] += a[ri] * kv[ci];
        }
        float tm[4];
#pragma unroll
        for (int ri = 0; ri < 4; ri++) {
            float mm = -1e30f;
#pragma unroll
            for (int ci = 0; ci < 4; ci++) { s[ri][ci] *= sc; mm = fmaxf(mm, s[ri][ci]); }
            tm[ri] = mm;
        }
#pragma unroll
        for (int off = 1; off < 16; off <<= 1)
#pragma unroll
            for (int ri = 0; ri < 4; ri++)
                tm[ri] = fmaxf(tm[ri], __shfl_xor_sync(0xffffffffu, tm[ri], off));
#pragma unroll
        for (int ri = 0; ri < 4; ri++) {
            float mn = fmaxf(m[ri], tm[ri]);
            float corr = expf(m[ri] - mn);
            m[ri] = mn;
            l[ri] *= corr;
            O[ri][0] *= corr;
            O[ri][1] *= corr;
        }
#pragma unroll
        for (int ri = 0; ri < 4; ri++) {
            float lp = 0.f;
#pragma unroll
            for (int ci = 0; ci < 4; ci++) {
                float p = expf(s[ri][ci] - m[ri]);
                Ss[(ty * 4 + ri) * 65 + tx * 4 + ci] = p;
                lp += p;
            }
            l[ri] += lp;
        }
        __syncthreads();
#pragma unroll 4
        for (int c = 0; c < 64; c++) {
            float v0 = Vs[c * 33 + tx * 2];
            float v1 = Vs[c * 33 + tx * 2 + 1];
#pragma unroll
            for (int ri = 0; ri < 4; ri++) {
                float p = Ss[(ty * 4 + ri) * 65 + c];
                O[ri][0] += p * v0;
                O[ri][1] += p * v1;
            }
        }
    }
#pragma unroll
    for (int off = 1; off < 16; off <<= 1)
#pragma unroll
        for (int ri = 0; ri < 4; ri++)
            l[ri] += __shfl_xor_sync(0xffffffffu, l[ri], off);
#pragma unroll
    for (int ri = 0; ri < 4; ri++) {
        float inv = 1.f / l[ri];
        int n = n0 + ty * 4 + ri;
#pragma unroll
        for (int dj = 0; dj < 2; dj++) {
            int d = tx * 2 + dj;
            float v = g_v[(bh * 1024 + n) * 32 + d] + O[ri][dj] * inv;
            g_xv[(b * 1024 + n) * 128 + h * 32 + d] = v;
        }
    }
}

// ---------------- output proj + residual, transposed store -----------------
__global__ __launch_bounds__(256) void k_proj(const float* __restrict__ proj_w, const float* __restrict__ proj_b) {
    __shared__ float As[64 * 65], Bs[64 * 65];
    int b = blockIdx.z;
    int n0 = blockIdx.x * 64, j0 = blockIdx.y * 64;
    int tx = threadIdx.x, ty = threadIdx.y, tid = ty * 16 + tx;
    float acc[4][4] = {};
    for (int kc = 0; kc < 2; kc++) {
        __syncthreads();
        for (int idx = tid; idx < 4096; idx += 256) {
            int r = idx >> 6, kk = idx & 63;
            As[r * 65 + kk] = g_xv[(b * 1024 + n0 + r) * 128 + kc * 64 + kk];
            Bs[r * 65 + kk] = proj_w[(j0 + r) * 128 + kc * 64 + kk];
        }
        __syncthreads();
#pragma unroll 8
        for (int kk = 0; kk < 64; kk++) {
            float a[4], w[4];
#pragma unroll
            for (int i = 0; i < 4; i++) a[i] = As[(i * 16 + tx) * 65 + kk];
#pragma unroll
            for (int j = 0; j < 4; j++) w[j] = Bs[(j * 16 + ty) * 65 + kk];
#pragma unroll
            for (int i = 0; i < 4; i++)
#pragma unroll
                for (int j = 0; j < 4; j++) acc[i][j] += a[i] * w[j];
        }
    }
#pragma unroll
    for (int i = 0; i < 4; i++)
#pragma unroll
        for (int j = 0; j < 4; j++) {
            int n = n0 + i * 16 + tx;
            int jj = j0 + j * 16 + ty;
            float v = acc[i][j] + proj_b[jj] + g_ori[(b * 1024 + n) * 128 + jj];
            g_x2[(b * 128 + jj) * 1024 + n] = v;
        }
}

// ---------------- token conv1d (128x128xk5 GEMM) + residual ----------------
__global__ __launch_bounds__(256) void k_conv1d() {
    __shared__ float Xs[32 * 132];
    __shared__ float Ws[32 * 64];
    int b = blockIdx.z, co0 = blockIdx.y * 64, n0 = blockIdx.x * 128;
    int tx = threadIdx.x, ty = threadIdx.y, tid = ty * 32 + tx;
    float acc[8][4] = {};
    for (int cc = 0; cc < 4; cc++) {
        for (int k = 0; k < 5; k++) {
            __syncthreads();
            if (k == 0) {
                for (int idx = tid; idx < 4224; idx += 256) {
                    int ci = idx / 132, t = idx % 132;
                    int n = n0 - 2 + t;
                    Xs[idx] = (n >= 0 && n < 1024) ? g_x2[(b * 128 + cc * 32 + ci) * 1024 + n] : 0.f;
                }
            }
            for (int idx = tid; idx < 2048; idx += 256) {
                int ci = idx >> 6, col = idx & 63;
                Ws[idx] = g_wc1[(k * 128 + cc * 32 + ci) * 128 + co0 + col];
            }
            __syncthreads();
#pragma unroll 4
            for (int ci = 0; ci < 32; ci++) {
                float4 w0 = *(const float4*)&Ws[ci * 64 + ty * 8];
                float4 w1 = *(const float4*)&Ws[ci * 64 + ty * 8 + 4];
                float w[8] = {w0.x, w0.y, w0.z, w0.w, w1.x, w1.y, w1.z, w1.w};
                float x[4];
#pragma unroll
                for (int j = 0; j < 4; j++) x[j] = Xs[ci * 132 + tx + 32 * j + k];
#pragma unroll
                for (int i = 0; i < 8; i++)
#pragma unroll
                    for (int j = 0; j < 4; j++) acc[i][j] += w[i] * x[j];
            }
        }
    }
#pragma unroll
    for (int i = 0; i < 8; i++)
#pragma unroll
        for (int j = 0; j < 4; j++) {
            int co = co0 + ty * 8 + i, n = n0 + tx + 32 * j;
            g_y2[(b * 128 + co) * 1024 + n] = acc[i][j] + g_x2[(b * 128 + co) * 1024 + n];
        }
}

// ---------------- bilinear 32->96 upsample (align_corners) -----------------
__global__ void k_up(float* __restrict__ out) {
    int j = threadIdx.x;
    int i = blockIdx.x * 4 + threadIdx.y;
    int c = blockIdx.y, b = blockIdx.z;
    const float sc = 31.0f / 95.0f;
    float cy = (float)i * sc;
    int i0 = (int)cy;
    float wy = cy - (float)i0;
    int i1 = min(i0 + 1, 31);
    float cx = (float)j * sc;
    int j0 = (int)cx;
    float wx = cx - (float)j0;
    int j1 = min(j0 + 1, 31);
    const float* Y = &g_y2[(b * 128 + c) * 1024];
    float v00 = Y[i0 * 32 + j0], v10 = Y[i1 * 32 + j0];
    float v01 = Y[i0 * 32 + j1], v11 = Y[i1 * 32 + j1];
    float a0 = v00 * (1.f - wy) + v10 * wy;
    float a1 = v01 * (1.f - wy) + v11 * wy;
    out[((b * 128 + c) * 96 + i) * 96 + j] = a0 * (1.f - wx) + a1 * wx;
}

// ---------------- launch ----------------------------------------------------
extern "C" void kernel_launch(void* const* d_in, const int* in_sizes, int n_in,
                              void* d_out, int out_size) {
    const float* s1     = (const float*)d_in[0];
    const float* o      = (const float*)d_in[1];
    const int*   index  = (const int*)  d_in[2];
    const float* pe_w   = (const float*)d_in[3];
    const float* bn_g   = (const float*)d_in[4];
    const float* bn_b   = (const float*)d_in[5];
    const float* bn_m   = (const float*)d_in[6];
    const float* bn_v   = (const float*)d_in[7];
    const float* lnx_g  = (const float*)d_in[8];
    const float* lnx_b  = (const float*)d_in[9];
    const float* lny_g  = (const float*)d_in[10];
    const float* lny_b  = (const float*)d_in[11];
    const float* qkv_w  = (const float*)d_in[12];
    const float* qkv_b  = (const float*)d_in[13];
    const float* yv_w   = (const float*)d_in[14];
    const float* yv_b   = (const float*)d_in[15];
    const float* proj_w = (const float*)d_in[16];
    const float* proj_b = (const float*)d_in[17];
    const float* c1d_w  = (const float*)d_in[18];
    float* out = (float*)d_out;

    k_repack   <<<320, 256>>>(pe_w, c1d_w);
    k_transpose<<<dim3(3, 96, 64), dim3(32, 32)>>>(s1);
    k_peconv   <<<dim3(192, 16), dim3(32, 8)>>>(index, bn_g, bn_b, bn_m, bn_v);
    k_pool_short<<<dim3(1024, 16), 128>>>(lny_g, lny_b);
    k_pool_o   <<<dim3(32, 4, 16), 256>>>(o);
    k_ln_of    <<<dim3(1024, 16), 128>>>(lnx_g, lnx_b);
    k_qkv      <<<dim3(16, 6, 16), dim3(16, 16)>>>(qkv_w, qkv_b);
    k_yvp      <<<dim3(16, 2, 16), dim3(16, 16)>>>(yv_w, yv_b);
    k_attn     <<<dim3(16, 64), dim3(16, 16)>>>();
    k_proj     <<<dim3(16, 2, 16), dim3(16, 16)>>>(proj_w, proj_b);
    k_conv1d   <<<dim3(8, 2, 16), dim3(32, 8)>>>();
    k_up       <<<dim3(24, 128, 16), dim3(96, 4)>>>(out);
}

// round 3
// speedup vs baseline: 1.0462x; 1.0462x over previous
#include <cuda_runtime.h>

typedef unsigned long long ull;

// ---------------- f32x2 helpers -------------------------------------------
__device__ __forceinline__ void fma2(ull& d, ull a, ull b) {
    asm("fma.rn.f32x2 %0, %1, %2, %0;" : "+l"(d) : "l"(a), "l"(b));
}
__device__ __forceinline__ ull dup2(float x) {
    ull r; asm("mov.b64 %0, {%1, %1};" : "=l"(r) : "f"(x)); return r;
}
__device__ __forceinline__ float2 up2(ull v) {
    float2 f; asm("mov.b64 {%0, %1}, %2;" : "=f"(f.x), "=f"(f.y) : "l"(v)); return f;
}
__device__ __forceinline__ float ex2(float x) {
    float r; asm("ex2.approx.ftz.f32 %0, %1;" : "=f"(r) : "f"(x)); return r;
}

// ---------------- scratch (device globals; no allocations) ----------------
__device__ float g_x   [18874368];   // [16][64][18432] patch-major im2col of s1
__device__ float g_z   [18874368];   // conv+bn+relu+mask output
__device__ float g_ori [2097152];    // [16][1024][128] pooled short tokens
__device__ float g_sn  [2097152];    // LN(ori)
__device__ float g_ofr [2097152];    // pooled o tokens (raw)
__device__ float g_of  [2097152];    // LN(of)
__device__ float g_q   [2097152];    // [16][4][1024][32]  (pre-scaled)
__device__ float g_k   [2097152];
__device__ float g_v   [2097152];
__device__ float g_yv  [2097152];
__device__ float g_xv  [2097152];    // [16][1024][128]
__device__ float g_x2  [2097152];    // [16][128][1024]
__device__ float g_y2  [2097152];    // conv1d output
__device__ float g_wpe [20480];      // [5][64pi][64po]
__device__ float g_wc1 [81920];      // [5][128ci][128co]

// ---------------- weight repack (k-major -> coalescable) -------------------
__global__ void k_repack(const float* __restrict__ pe_w, const float* __restrict__ c1d_w) {
    int idx = blockIdx.x * 256 + threadIdx.x;
    if (idx < 20480) {
        int k = idx / 4096, r = idx % 4096, pi = r / 64, po = r % 64;
        g_wpe[idx] = pe_w[(po * 64 + pi) * 5 + k];
    }
    if (idx < 81920) {
        int k = idx / 16384, r = idx % 16384, ci = r / 128, co = r % 128;
        g_wc1[idx] = c1d_w[(co * 128 + ci) * 5 + k];
    }
}

// ---------------- s1 -> patch-major layout (smem transpose) ----------------
__global__ void k_transpose(const float* __restrict__ s1) {
    __shared__ float t[32][33];
    int b = blockIdx.z >> 2, cg = blockIdx.z & 3;
    int row = blockIdx.y;               // 0..95  = h*12+p1
    int W0 = blockIdx.x * 32;
    int tx = threadIdx.x, ty = threadIdx.y;
    t[ty][tx] = s1[((b * 128 + cg * 32 + ty) * 96 + row) * 96 + W0 + tx];
    __syncthreads();
    int Wl = W0 + ty;
    int w = Wl / 12, p2 = Wl % 12;
    int h = row / 12, p1 = row % 12;
    g_x[(b * 64 + h * 8 + w) * 18432 + (p1 * 12 + p2) * 128 + cg * 32 + tx] = t[tx][ty];
}

// ---------------- patch-embed conv (f32x2) + BN + ReLU + mask --------------
__global__ __launch_bounds__(256) void k_peconv(
    const int* __restrict__ index,
    const float* __restrict__ bn_g, const float* __restrict__ bn_b,
    const float* __restrict__ bn_m, const float* __restrict__ bn_v) {
    __shared__ __align__(16) float Xs[32 * 132];
    __shared__ __align__(16) float Ws[32 * 64];
    int b = blockIdx.y;
    int f0 = blockIdx.x * 128;
    int tx = threadIdx.x, ty = threadIdx.y;
    int tid = ty * 32 + tx;

    ull acc[4][4];
#pragma unroll
    for (int p = 0; p < 4; p++)
#pragma unroll
        for (int j = 0; j < 4; j++) acc[p][j] = 0ull;

    for (int cc = 0; cc < 2; cc++) {
        __syncthreads();
        for (int idx = tid; idx < 4224; idx += 256) {
            int pil = idx / 132, t = idx % 132;
            int f = f0 - 2 + t;
            Xs[idx] = (f >= 0 && f < 18432) ? g_x[(b * 64 + cc * 32 + pil) * 18432 + f] : 0.f;
        }
        for (int k = 0; k < 5; k++) {
            __syncthreads();
            for (int idx = tid; idx < 2048; idx += 256)
                Ws[idx] = g_wpe[k * 4096 + cc * 2048 + idx];
            __syncthreads();
#pragma unroll 4
            for (int pil = 0; pil < 32; pil++) {
                ulonglong2 wA = *(const ulonglong2*)&Ws[pil * 64 + ty * 8];
                ulonglong2 wB = *(const ulonglong2*)&Ws[pil * 64 + ty * 8 + 4];
                ull wp[4] = {wA.x, wA.y, wB.x, wB.y};
                ull xd[4];
#pragma unroll
                for (int j = 0; j < 4; j++)
                    xd[j] = dup2(Xs[pil * 132 + tx + 32 * j + k]);
#pragma unroll
                for (int p = 0; p < 4; p++)
#pragma unroll
                    for (int j = 0; j < 4; j++) fma2(acc[p][j], wp[p], xd[j]);
            }
        }
        __syncthreads();
    }

    int pidx0 = (index[0] / 12) * 8 + index[1] / 12;
    int pidx1 = (index[2] / 12) * 8 + index[3] / 12;
    int pidx2 = (index[4] / 12) * 8 + index[5] / 12;
    int pidx3 = (index[6] / 12) * 8 + index[7] / 12;

#pragma unroll
    for (int p = 0; p < 4; p++) {
        int po0 = ty * 8 + p * 2;
#pragma unroll
        for (int lane = 0; lane < 2; lane++) {
            int po = po0 + lane;
            bool sel = (po == pidx0) | (po == pidx1) | (po == pidx2) | (po == pidx3);
            float mm = bn_m[po];
            float invs = rsqrtf(bn_v[po] + 1e-5f);
            float gg = bn_g[po], bb = bn_b[po];
#pragma unroll
            for (int j = 0; j < 4; j++) {
                float2 f2 = up2(acc[p][j]);
                float v = (lane ? f2.y : f2.x);
                v = (v - mm) * invs * gg + bb;
                v = fmaxf(v, 0.f);
                if (!sel) v *= v;
                g_z[(b * 64 + po) * 18432 + f0 + tx + 32 * j] = v;
            }
        }
    }
}

// ---------------- LN helper (blockDim.x == 128) ----------------------------
__device__ __forceinline__ void ln_stats128(float v, float& mean, float& rstd) {
    float s = v, s2 = v * v;
#pragma unroll
    for (int off = 16; off; off >>= 1) {
        s  += __shfl_xor_sync(0xffffffffu, s,  off);
        s2 += __shfl_xor_sync(0xffffffffu, s2, off);
    }
    __shared__ float sm[4], sm2[4];
    int w = threadIdx.x >> 5, ln = threadIdx.x & 31;
    if (ln == 0) { sm[w] = s; sm2[w] = s2; }
    __syncthreads();
    s  = sm[0] + sm[1] + sm[2] + sm[3];
    s2 = sm2[0] + sm2[1] + sm2[2] + sm2[3];
    mean = s * (1.f / 128.f);
    float var = s2 * (1.f / 128.f) - mean * mean;
    rstd = rsqrtf(var + 1e-5f);
}

// ---------------- 3x3 pool of z -> ori tokens + LN -> sn -------------------
__global__ void k_pool_short(const float* __restrict__ lny_g, const float* __restrict__ lny_b) {
    int n = blockIdx.x, b = blockIdx.y, c = threadIdx.x;
    int oh = n >> 5, ow = n & 31;
    int p = (oh >> 2) * 8 + (ow >> 2);
    int base = (b * 64 + p) * 18432;
    int p1s = (oh & 3) * 3, p2s = (ow & 3) * 3;
    float s = 0.f;
#pragma unroll
    for (int r = 0; r < 3; r++)
#pragma unroll
        for (int t = 0; t < 3; t++)
            s += g_z[base + ((p1s + r) * 12 + p2s + t) * 128 + c];
    s *= (1.f / 9.f);
    g_ori[(b * 1024 + n) * 128 + c] = s;
    float mean, rstd;
    ln_stats128(s, mean, rstd);
    g_sn[(b * 1024 + n) * 128 + c] = (s - mean) * rstd * lny_g[c] + lny_b[c];
}

// ---------------- 2x2 pool of o, transposed to token-major -----------------
__global__ void k_pool_o(const float* __restrict__ o) {
    __shared__ float T[32][33];
    int oh = blockIdx.x, cg = blockIdx.y, b = blockIdx.z;
    int tid = threadIdx.x;
#pragma unroll
    for (int it = 0; it < 4; it++) {
        int idx = it * 256 + tid;
        int cl = idx >> 5, ow = idx & 31;
        const float* p = &o[((b * 128 + cg * 32 + cl) * 64 + 2 * oh) * 64 + 2 * ow];
        T[cl][ow] = 0.25f * (p[0] + p[1] + p[64] + p[65]);
    }
    __syncthreads();
#pragma unroll
    for (int it = 0; it < 4; it++) {
        int idx = it * 256 + tid;
        int cl = idx & 31, ow = idx >> 5;
        g_ofr[(b * 1024 + oh * 32 + ow) * 128 + cg * 32 + cl] = T[cl][ow];
    }
}

__global__ void k_ln_of(const float* __restrict__ lnx_g, const float* __restrict__ lnx_b) {
    int n = blockIdx.x, b = blockIdx.y, c = threadIdx.x;
    float v = g_ofr[(b * 1024 + n) * 128 + c];
    float mean, rstd;
    ln_stats128(v, mean, rstd);
    g_of[(b * 1024 + n) * 128 + c] = (v - mean) * rstd * lnx_g[c] + lnx_b[c];
}

// ---------------- generic 64x64 token GEMM body (f32x2) --------------------
// As: [r=n][kk] stride 65; Bs: [kk][c] stride 66 (c-pairs 8B aligned).
// thread (tx 0..15, ty 0..15): rows {i*16+tx}, cols {ty*4 .. ty*4+3}.
#define GEMM_BODY(SRC, W)                                                        \
    ull s2[4][2];                                                                \
    _Pragma("unroll")                                                            \
    for (int i = 0; i < 4; i++) { s2[i][0] = 0ull; s2[i][1] = 0ull; }            \
    for (int kc = 0; kc < 2; kc++) {                                             \
        __syncthreads();                                                         \
        for (int idx = tid; idx < 4096; idx += 256) {                            \
            int r = idx >> 6, kk = idx & 63;                                     \
            As[r * 65 + kk] = SRC[(b * 1024 + n0 + r) * 128 + kc * 64 + kk];     \
            Bs[kk * 66 + r] = W[(j0 + r) * 128 + kc * 64 + kk];                  \
        }                                                                        \
        __syncthreads();                                                         \
        _Pragma("unroll 8")                                                      \
        for (int kk = 0; kk < 64; kk++) {                                        \
            ull b01 = *(const ull*)&Bs[kk * 66 + ty * 4];                        \
            ull b23 = *(const ull*)&Bs[kk * 66 + ty * 4 + 2];                    \
            _Pragma("unroll")                                                    \
            for (int i = 0; i < 4; i++) {                                        \
                ull ad = dup2(As[(i * 16 + tx) * 65 + kk]);                      \
                fma2(s2[i][0], ad, b01);                                         \
                fma2(s2[i][1], ad, b23);                                         \
            }                                                                    \
        }                                                                        \
    }

// ---------------- QKV projection -------------------------------------------
__global__ __launch_bounds__(256) void k_qkv(const float* __restrict__ qkv_w, const float* __restrict__ qkv_b) {
    __shared__ float As[64 * 65];
    __shared__ __align__(16) float Bs[64 * 66];
    int b = blockIdx.z;
    int n0 = blockIdx.x * 64, j0 = blockIdx.y * 64;
    int tx = threadIdx.x, ty = threadIdx.y, tid = ty * 16 + tx;
    GEMM_BODY(g_of, qkv_w)
    const float qs = 0.17677669529663687f * 1.4426950408889634f;
#pragma unroll
    for (int i = 0; i < 4; i++)
#pragma unroll
        for (int pr = 0; pr < 2; pr++) {
            float2 f2 = up2(s2[i][pr]);
            int n = n0 + i * 16 + tx;
#pragma unroll
            for (int lane = 0; lane < 2; lane++) {
                int jj = j0 + ty * 4 + pr * 2 + lane;
                float v = (lane ? f2.y : f2.x) + qkv_b[jj];
                int which = jj >> 7, rem = jj & 127, h = rem >> 5, d = rem & 31;
                if (which == 0)
                    g_q[((b * 4 + h) * 1024 + n) * 32 + d] = v * qs;   // fold softmax scale*log2e
                else if (which == 1)
                    g_k[((b * 4 + h) * 1024 + n) * 32 + d] = v;
                else
                    g_v[((b * 4 + h) * 1024 + n) * 32 + d] = v;
            }
        }
}

// ---------------- YV projection --------------------------------------------
__global__ __launch_bounds__(256) void k_yvp(const float* __restrict__ yv_w, const float* __restrict__ yv_b) {
    __shared__ float As[64 * 65];
    __shared__ __align__(16) float Bs[64 * 66];
    int b = blockIdx.z;
    int n0 = blockIdx.x * 64, j0 = blockIdx.y * 64;
    int tx = threadIdx.x, ty = threadIdx.y, tid = ty * 16 + tx;
    GEMM_BODY(g_sn, yv_w)
#pragma unroll
    for (int i = 0; i < 4; i++)
#pragma unroll
        for (int pr = 0; pr < 2; pr++) {
            float2 f2 = up2(s2[i][pr]);
            int n = n0 + i * 16 + tx;
#pragma unroll
            for (int lane = 0; lane < 2; lane++) {
                int jj = j0 + ty * 4 + pr * 2 + lane;
                int h = jj >> 5, d = jj & 31;
                g_yv[((b * 4 + h) * 1024 + n) * 32 + d] = (lane ? f2.y : f2.x) + yv_b[jj];
            }
        }
}

// ---------------- flash attention (no-max softmax, ex2, f32x2) -------------
__global__ __launch_bounds__(256) void k_attn() {
    __shared__ float Qs[64 * 33];
    __shared__ __align__(16) float Ks[32 * 66];   // [d][r]
    __shared__ __align__(16) float Vs[64 * 34];   // [r][d]
    __shared__ float Ss[64 * 65];
    int bh = blockIdx.y;
    int n0 = blockIdx.x * 64;
    int b = bh >> 2, h = bh & 3;
    int tx = threadIdx.x, ty = threadIdx.y, tid = ty * 16 + tx;

    for (int idx = tid; idx < 2048; idx += 256) {
        int r = idx >> 5, d = idx & 31;
        Qs[r * 33 + d] = g_q[(bh * 1024 + n0 + r) * 32 + d];   // already scaled by sc*log2e
    }

    float l[4] = {0, 0, 0, 0};
    ull O2[4] = {0ull, 0ull, 0ull, 0ull};

    for (int ct = 0; ct < 16; ct++) {
        __syncthreads();
        for (int idx = tid; idx < 2048; idx += 256) {
            int r = idx >> 5, d = idx & 31;
            Ks[d * 66 + r] = g_k [(bh * 1024 + ct * 64 + r) * 32 + d];
            Vs[r * 34 + d] = g_yv[(bh * 1024 + ct * 64 + r) * 32 + d];
        }
        __syncthreads();

        ull s2[4][2];
#pragma unroll
        for (int ri = 0; ri < 4; ri++) { s2[ri][0] = 0ull; s2[ri][1] = 0ull; }
#pragma unroll 8
        for (int d = 0; d < 32; d++) {
            ull kv01 = *(const ull*)&Ks[d * 66 + tx * 4];
            ull kv23 = *(const ull*)&Ks[d * 66 + tx * 4 + 2];
#pragma unroll
            for (int ri = 0; ri < 4; ri++) {
                ull ad = dup2(Qs[(ty * 4 + ri) * 33 + d]);
                fma2(s2[ri][0], ad, kv01);
                fma2(s2[ri][1], ad, kv23);
            }
        }
#pragma unroll
        for (int ri = 0; ri < 4; ri++) {
            float2 sA = up2(s2[ri][0]);
            float2 sB = up2(s2[ri][1]);
            float p0 = ex2(sA.x), p1 = ex2(sA.y), p2 = ex2(sB.x), p3 = ex2(sB.y);
            float* row = &Ss[(ty * 4 + ri) * 65 + tx * 4];
            row[0] = p0; row[1] = p1; row[2] = p2; row[3] = p3;
            l[ri] += (p0 + p1) + (p2 + p3);
        }
        __syncwarp();   // Ss rows are produced/consumed within one warp
#pragma unroll 4
        for (int c = 0; c < 64; c++) {
            ull v01 = *(const ull*)&Vs[c * 34 + tx * 2];
#pragma unroll
            for (int ri = 0; ri < 4; ri++)
                fma2(O2[ri], dup2(Ss[(ty * 4 + ri) * 65 + c]), v01);
        }
        __syncwarp();
    }
#pragma unroll
    for (int off = 1; off < 16; off <<= 1)
#pragma unroll
        for (int ri = 0; ri < 4; ri++)
            l[ri] += __shfl_xor_sync(0xffffffffu, l[ri], off);
#pragma unroll
    for (int ri = 0; ri < 4; ri++) {
        float inv = 1.f / l[ri];
        int n = n0 + ty * 4 + ri;
        float2 o = up2(O2[ri]);
        int d0 = tx * 2;
        g_xv[(b * 1024 + n) * 128 + h * 32 + d0]     = g_v[(bh * 1024 + n) * 32 + d0]     + o.x * inv;
        g_xv[(b * 1024 + n) * 128 + h * 32 + d0 + 1] = g_v[(bh * 1024 + n) * 32 + d0 + 1] + o.y * inv;
    }
}

// ---------------- output proj + residual, transposed store -----------------
__global__ __launch_bounds__(256) void k_proj(const float* __restrict__ proj_w, const float* __restrict__ proj_b) {
    __shared__ float As[64 * 65];
    __shared__ __align__(16) float Bs[64 * 66];
    int b = blockIdx.z;
    int n0 = blockIdx.x * 64, j0 = blockIdx.y * 64;
    int tx = threadIdx.x, ty = threadIdx.y, tid = ty * 16 + tx;
    GEMM_BODY(g_xv, proj_w)
#pragma unroll
    for (int i = 0; i < 4; i++)
#pragma unroll
        for (int pr = 0; pr < 2; pr++) {
            float2 f2 = up2(s2[i][pr]);
            int n = n0 + i * 16 + tx;
#pragma unroll
            for (int lane = 0; lane < 2; lane++) {
                int jj = j0 + ty * 4 + pr * 2 + lane;
                float v = (lane ? f2.y : f2.x) + proj_b[jj] + g_ori[(b * 1024 + n) * 128 + jj];
                g_x2[(b * 128 + jj) * 1024 + n] = v;
            }
        }
}

// ---------------- token conv1d (f32x2) + residual --------------------------
__global__ __launch_bounds__(256) void k_conv1d() {
    __shared__ __align__(16) float Xs[32 * 132];
    __shared__ __align__(16) float Ws[32 * 64];
    int b = blockIdx.z, co0 = blockIdx.y * 64, n0 = blockIdx.x * 128;
    int tx = threadIdx.x, ty = threadIdx.y, tid = ty * 32 + tx;

    ull acc[4][4];
#pragma unroll
    for (int p = 0; p < 4; p++)
#pragma unroll
        for (int j = 0; j < 4; j++) acc[p][j] = 0ull;

    for (int cc = 0; cc < 4; cc++) {
        __syncthreads();
        for (int idx = tid; idx < 4224; idx += 256) {
            int cil = idx / 132, t = idx % 132;
            int n = n0 - 2 + t;
            Xs[idx] = (n >= 0 && n < 1024) ? g_x2[(b * 128 + cc * 32 + cil) * 1024 + n] : 0.f;
        }
        for (int k = 0; k < 5; k++) {
            __syncthreads();
            {
                int base = (k * 128 + cc * 32) * 128 + co0;
                for (int idx = tid; idx < 2048; idx += 256) {
                    int cil = idx >> 6, col = idx & 63;
                    Ws[cil * 64 + col] = g_wc1[base + cil * 128 + col];
                }
            }
            __syncthreads();
#pragma unroll 4
            for (int cil = 0; cil < 32; cil++) {
                ulonglong2 wA = *(const ulonglong2*)&Ws[cil * 64 + ty * 8];
                ulonglong2 wB = *(const ulonglong2*)&Ws[cil * 64 + ty * 8 + 4];
                ull wp[4] = {wA.x, wA.y, wB.x, wB.y};
                ull xd[4];
#pragma unroll
                for (int j = 0; j < 4; j++)
                    xd[j] = dup2(Xs[cil * 132 + tx + 32 * j + k]);
#pragma unroll
                for (int p = 0; p < 4; p++)
#pragma unroll
                    for (int j = 0; j < 4; j++) fma2(acc[p][j], wp[p], xd[j]);
            }
        }
        __syncthreads();
    }
#pragma unroll
    for (int p = 0; p < 4; p++)
#pragma unroll
        for (int lane = 0; lane < 2; lane++) {
            int co = co0 + ty * 8 + p * 2 + lane;
#pragma unroll
            for (int j = 0; j < 4; j++) {
                float2 f2 = up2(acc[p][j]);
                int n = n0 + tx + 32 * j;
                g_y2[(b * 128 + co) * 1024 + n] =
                    (lane ? f2.y : f2.x) + g_x2[(b * 128 + co) * 1024 + n];
            }
        }
}

// ---------------- bilinear 32->96 upsample (align_corners) -----------------
__global__ void k_up(float* __restrict__ out) {
    int j = threadIdx.x;
    int i = blockIdx.x * 4 + threadIdx.y;
    int c = blockIdx.y, b = blockIdx.z;
    const float sc = 31.0f / 95.0f;
    float cy = (float)i * sc;
    int i0 = (int)cy;
    float wy = cy - (float)i0;
    int i1 = min(i0 + 1, 31);
    float cx = (float)j * sc;
    int j0 = (int)cx;
    float wx = cx - (float)j0;
    int j1 = min(j0 + 1, 31);
    const float* Y = &g_y2[(b * 128 + c) * 1024];
    float v00 = Y[i0 * 32 + j0], v10 = Y[i1 * 32 + j0];
    float v01 = Y[i0 * 32 + j1], v11 = Y[i1 * 32 + j1];
    float a0 = v00 * (1.f - wy) + v10 * wy;
    float a1 = v01 * (1.f - wy) + v11 * wy;
    out[((b * 128 + c) * 96 + i) * 96 + j] = a0 * (1.f - wx) + a1 * wx;
}

// ---------------- launch ----------------------------------------------------
extern "C" void kernel_launch(void* const* d_in, const int* in_sizes, int n_in,
                              void* d_out, int out_size) {
    const float* s1     = (const float*)d_in[0];
    const float* o      = (const float*)d_in[1];
    const int*   index  = (const int*)  d_in[2];
    const float* pe_w   = (const float*)d_in[3];
    const float* bn_g   = (const float*)d_in[4];
    const float* bn_b   = (const float*)d_in[5];
    const float* bn_m   = (const float*)d_in[6];
    const float* bn_v   = (const float*)d_in[7];
    const float* lnx_g  = (const float*)d_in[8];
    const float* lnx_b  = (const float*)d_in[9];
    const float* lny_g  = (const float*)d_in[10];
    const float* lny_b  = (const float*)d_in[11];
    const float* qkv_w  = (const float*)d_in[12];
    const float* qkv_b  = (const float*)d_in[13];
    const float* yv_w   = (const float*)d_in[14];
    const float* yv_b   = (const float*)d_in[15];
    const float* proj_w = (const float*)d_in[16];
    const float* proj_b = (const float*)d_in[17];
    const float* c1d_w  = (const float*)d_in[18];
    float* out = (float*)d_out;

    k_repack    <<<320, 256>>>(pe_w, c1d_w);
    k_transpose <<<dim3(3, 96, 64), dim3(32, 32)>>>(s1);
    k_peconv    <<<dim3(144, 16), dim3(32, 8)>>>(index, bn_g, bn_b, bn_m, bn_v);
    k_pool_short<<<dim3(1024, 16), 128>>>(lny_g, lny_b);
    k_pool_o    <<<dim3(32, 4, 16), 256>>>(o);
    k_ln_of     <<<dim3(1024, 16), 128>>>(lnx_g, lnx_b);
    k_qkv       <<<dim3(16, 6, 16), dim3(16, 16)>>>(qkv_w, qkv_b);
    k_yvp       <<<dim3(16, 2, 16), dim3(16, 16)>>>(yv_w, yv_b);
    k_attn      <<<dim3(16, 64), dim3(16, 16)>>>();
    k_proj      <<<dim3(16, 2, 16), dim3(16, 16)>>>(proj_w, proj_b);
    k_conv1d    <<<dim3(8, 2, 16), dim3(32, 8)>>>();
    k_up        <<<dim3(24, 128, 16), dim3(96, 4)>>>(out);
}

// round 5
// speedup vs baseline: 1.3716x; 1.3109x over previous
#include <cuda_runtime.h>

typedef unsigned long long ull;
typedef unsigned int uint;

// ---------------- f32x2 / tf32 helpers ------------------------------------
__device__ __forceinline__ void fma2(ull& d, ull a, ull b) {
    asm("fma.rn.f32x2 %0, %1, %2, %0;" : "+l"(d) : "l"(a), "l"(b));
}
__device__ __forceinline__ ull dup2(float x) {
    ull r; asm("mov.b64 %0, {%1, %1};" : "=l"(r) : "f"(x)); return r;
}
__device__ __forceinline__ float2 up2(ull v) {
    float2 f; asm("mov.b64 {%0, %1}, %2;" : "=f"(f.x), "=f"(f.y) : "l"(v)); return f;
}
__device__ __forceinline__ float ex2(float x) {
    float r; asm("ex2.approx.ftz.f32 %0, %1;" : "=f"(r) : "f"(x)); return r;
}
__device__ __forceinline__ float tf32hi(float x) {
    uint u; asm("cvt.rna.tf32.f32 %0, %1;" : "=r"(u) : "f"(x));
    return __uint_as_float(u);
}
// D(16x8) += A(16x8) * B(8x8), tf32 inputs, fp32 accum
__device__ __forceinline__ void mma_tf32(float* c, const uint* a, uint b0, uint b1) {
    asm volatile(
        "mma.sync.aligned.m16n8k8.row.col.f32.tf32.tf32.f32 "
        "{%0,%1,%2,%3}, {%4,%5,%6,%7}, {%8,%9}, {%0,%1,%2,%3};"
        : "+f"(c[0]), "+f"(c[1]), "+f"(c[2]), "+f"(c[3])
        : "r"(a[0]), "r"(a[1]), "r"(a[2]), "r"(a[3]), "r"(b0), "r"(b1));
}

// ---------------- scratch (device globals; no allocations) ----------------
__device__ float g_x   [18874368];   // [16][64][18432] patch-major im2col of s1
__device__ float g_z   [18874368];   // conv+bn+relu+mask output
__device__ float g_ori [2097152];    // [16][1024][128] pooled short tokens
__device__ float g_sn  [2097152];    // LN(ori)
__device__ float g_ofr [2097152];    // pooled o tokens (raw)
__device__ float g_of  [2097152];    // LN(of)
__device__ float g_q   [2097152];    // [16][4][1024][32]  (pre-scaled by sc*log2e)
__device__ float g_k   [2097152];
__device__ float g_v   [2097152];
__device__ float g_yv  [2097152];
__device__ float g_xv  [2097152];    // [16][1024][128]
__device__ float g_x2  [2097152];    // [16][128][1024]
__device__ float g_y2  [2097152];    // conv1d output
__device__ float g_wc1 [81920];      // [5][128ci][128co]
__device__ float g_wa_hi[20480];     // pe weights, mma-fragment packed, tf32 hi
__device__ float g_wa_lo[20480];     // residual lo

// ---------------- weight repack --------------------------------------------
__global__ void k_repack(const float* __restrict__ pe_w, const float* __restrict__ c1d_w) {
    int idx = blockIdx.x * 256 + threadIdx.x;
    if (idx < 20480) {
        // fragment-packed A for peconv: [cc2][ch20][mt4][lane32][r4]
        int r = idx & 3, lane = (idx >> 2) & 31, mt = (idx >> 7) & 3;
        int chgl = idx >> 9;            // 0..39
        int cc = chgl / 20, ch = chgl % 20;
        int kk = ch >> 2, pc = ch & 3;
        int g = lane >> 2, t = lane & 3;
        int po = mt * 16 + g + (r & 1) * 8;
        int pi = cc * 32 + pc * 8 + t + ((r >> 1) & 1) * 4;
        float w = pe_w[(po * 64 + pi) * 5 + kk];
        float hi = tf32hi(w);
        g_wa_hi[idx] = hi;
        g_wa_lo[idx] = w - hi;
    }
    if (idx < 81920) {
        int k = idx / 16384, r = idx % 16384, ci = r / 128, co = r % 128;
        g_wc1[idx] = c1d_w[(co * 128 + ci) * 5 + k];
    }
}

// ---------------- s1 -> patch-major layout (smem transpose) ----------------
__global__ void k_transpose(const float* __restrict__ s1) {
    __shared__ float t[32][33];
    int b = blockIdx.z >> 2, cg = blockIdx.z & 3;
    int row = blockIdx.y;               // 0..95  = h*12+p1
    int W0 = blockIdx.x * 32;
    int tx = threadIdx.x, ty = threadIdx.y;
    t[ty][tx] = s1[((b * 128 + cg * 32 + ty) * 96 + row) * 96 + W0 + tx];
    __syncthreads();
    int Wl = W0 + ty;
    int w = Wl / 12, p2 = Wl % 12;
    int h = row / 12, p1 = row % 12;
    g_x[(b * 64 + h * 8 + w) * 18432 + (p1 * 12 + p2) * 128 + cg * 32 + tx] = t[tx][ty];
}

// ---------------- patch-embed conv via tf32 mma + BN + ReLU + mask ---------
// Per block: b = blockIdx.y, f tile of 128 = blockIdx.x. 8 warps:
// warp = mt(0..3: po tile of 16) x nh(0..1: f half of 64).
__global__ __launch_bounds__(256) void k_peconv(
    const int* __restrict__ index,
    const float* __restrict__ bn_g, const float* __restrict__ bn_b,
    const float* __restrict__ bn_m, const float* __restrict__ bn_v) {
    __shared__ float Xh[32 * 136];
    __shared__ float Xl[32 * 136];
    int b = blockIdx.y;
    int f0 = blockIdx.x * 128;
    int tid = threadIdx.x;
    int warp = tid >> 5, lane = tid & 31, g = lane >> 2, t = lane & 3;
    int mt = warp >> 1, nh = warp & 1;

    float acc[8][4];
#pragma unroll
    for (int nt = 0; nt < 8; nt++)
#pragma unroll
        for (int r = 0; r < 4; r++) acc[nt][r] = 0.f;

    for (int cc = 0; cc < 2; cc++) {
        __syncthreads();
        for (int idx = tid; idx < 32 * 132; idx += 256) {
            int pil = idx / 132, tc = idx % 132;
            int f = f0 - 2 + tc;
            float v = (f >= 0 && f < 18432) ? g_x[(b * 64 + cc * 32 + pil) * 18432 + f] : 0.f;
            float hi = tf32hi(v);
            Xh[pil * 136 + tc] = hi;
            Xl[pil * 136 + tc] = v - hi;
        }
        __syncthreads();
#pragma unroll 5
        for (int ch = 0; ch < 20; ch++) {
            int kk = ch >> 2, pc = ch & 3;
            float4 a4h = *(const float4*)&g_wa_hi[(((cc * 20 + ch) * 4 + mt) * 32 + lane) * 4];
            float4 a4l = *(const float4*)&g_wa_lo[(((cc * 20 + ch) * 4 + mt) * 32 + lane) * 4];
            uint ah[4] = {__float_as_uint(a4h.x), __float_as_uint(a4h.y),
                          __float_as_uint(a4h.z), __float_as_uint(a4h.w)};
            uint al[4] = {__float_as_uint(a4l.x), __float_as_uint(a4l.y),
                          __float_as_uint(a4l.z), __float_as_uint(a4l.w)};
            int r0 = (pc * 8 + t) * 136 + kk;
            int r1 = r0 + 4 * 136;
#pragma unroll
            for (int nt = 0; nt < 8; nt++) {
                int cofs = nh * 64 + nt * 8 + g;
                uint bh0 = __float_as_uint(Xh[r0 + cofs]);
                uint bh1 = __float_as_uint(Xh[r1 + cofs]);
                uint bl0 = __float_as_uint(Xl[r0 + cofs]);
                uint bl1 = __float_as_uint(Xl[r1 + cofs]);
                mma_tf32(acc[nt], ah, bh0, bh1);   // Ah*Bh
                mma_tf32(acc[nt], al, bh0, bh1);   // Al*Bh
                mma_tf32(acc[nt], ah, bl0, bl1);   // Ah*Bl
            }
        }
    }

    int pidx0 = (index[0] / 12) * 8 + index[1] / 12;
    int pidx1 = (index[2] / 12) * 8 + index[3] / 12;
    int pidx2 = (index[4] / 12) * 8 + index[5] / 12;
    int pidx3 = (index[6] / 12) * 8 + index[7] / 12;

    int poA = mt * 16 + g, poB = poA + 8;
    bool selA = (poA == pidx0) | (poA == pidx1) | (poA == pidx2) | (poA == pidx3);
    bool selB = (poB == pidx0) | (poB == pidx1) | (poB == pidx2) | (poB == pidx3);
    float mA = bn_m[poA], sA = rsqrtf(bn_v[poA] + 1e-5f), gA = bn_g[poA], bA = bn_b[poA];
    float mB = bn_m[poB], sB = rsqrtf(bn_v[poB] + 1e-5f), gB = bn_g[poB], bB = bn_b[poB];

#pragma unroll
    for (int nt = 0; nt < 8; nt++) {
        int f = f0 + nh * 64 + nt * 8 + 2 * t;
        float v0 = fmaxf((acc[nt][0] - mA) * sA * gA + bA, 0.f);
        float v1 = fmaxf((acc[nt][1] - mA) * sA * gA + bA, 0.f);
        if (!selA) { v0 *= v0; v1 *= v1; }
        *(float2*)&g_z[(b * 64 + poA) * 18432 + f] = make_float2(v0, v1);
        float v2 = fmaxf((acc[nt][2] - mB) * sB * gB + bB, 0.f);
        float v3 = fmaxf((acc[nt][3] - mB) * sB * gB + bB, 0.f);
        if (!selB) { v2 *= v2; v3 *= v3; }
        *(float2*)&g_z[(b * 64 + poB) * 18432 + f] = make_float2(v2, v3);
    }
}

// ---------------- LN helper (blockDim.x == 128) ----------------------------
__device__ __forceinline__ void ln_stats128(float v, float& mean, float& rstd) {
    float s = v, s2 = v * v;
#pragma unroll
    for (int off = 16; off; off >>= 1) {
        s  += __shfl_xor_sync(0xffffffffu, s,  off);
        s2 += __shfl_xor_sync(0xffffffffu, s2, off);
    }
    __shared__ float sm[4], sm2[4];
    int w = threadIdx.x >> 5, ln = threadIdx.x & 31;
    if (ln == 0) { sm[w] = s; sm2[w] = s2; }
    __syncthreads();
    s  = sm[0] + sm[1] + sm[2] + sm[3];
    s2 = sm2[0] + sm2[1] + sm2[2] + sm2[3];
    mean = s * (1.f / 128.f);
    float var = s2 * (1.f / 128.f) - mean * mean;
    rstd = rsqrtf(var + 1e-5f);
}

// ---------------- 3x3 pool of z -> ori tokens + LN -> sn -------------------
__global__ void k_pool_short(const float* __restrict__ lny_g, const float* __restrict__ lny_b) {
    int n = blockIdx.x, b = blockIdx.y, c = threadIdx.x;
    int oh = n >> 5, ow = n & 31;
    int p = (oh >> 2) * 8 + (ow >> 2);
    int base = (b * 64 + p) * 18432;
    int p1s = (oh & 3) * 3, p2s = (ow & 3) * 3;
    float s = 0.f;
#pragma unroll
    for (int r = 0; r < 3; r++)
#pragma unroll
        for (int t = 0; t < 3; t++)
            s += g_z[base + ((p1s + r) * 12 + p2s + t) * 128 + c];
    s *= (1.f / 9.f);
    g_ori[(b * 1024 + n) * 128 + c] = s;
    float mean, rstd;
    ln_stats128(s, mean, rstd);
    g_sn[(b * 1024 + n) * 128 + c] = (s - mean) * rstd * lny_g[c] + lny_b[c];
}

// ---------------- 2x2 pool of o, transposed to token-major -----------------
__global__ void k_pool_o(const float* __restrict__ o) {
    __shared__ float T[32][33];
    int oh = blockIdx.x, cg = blockIdx.y, b = blockIdx.z;
    int tid = threadIdx.x;
#pragma unroll
    for (int it = 0; it < 4; it++) {
        int idx = it * 256 + tid;
        int cl = idx >> 5, ow = idx & 31;
        const float* p = &o[((b * 128 + cg * 32 + cl) * 64 + 2 * oh) * 64 + 2 * ow];
        T[cl][ow] = 0.25f * (p[0] + p[1] + p[64] + p[65]);
    }
    __syncthreads();
#pragma unroll
    for (int it = 0; it < 4; it++) {
        int idx = it * 256 + tid;
        int cl = idx & 31, ow = idx >> 5;
        g_ofr[(b * 1024 + oh * 32 + ow) * 128 + cg * 32 + cl] = T[cl][ow];
    }
}

__global__ void k_ln_of(const float* __restrict__ lnx_g, const float* __restrict__ lnx_b) {
    int n = blockIdx.x, b = blockIdx.y, c = threadIdx.x;
    float v = g_ofr[(b * 1024 + n) * 128 + c];
    float mean, rstd;
    ln_stats128(v, mean, rstd);
    g_of[(b * 1024 + n) * 128 + c] = (v - mean) * rstd * lnx_g[c] + lnx_b[c];
}

// ---------------- generic 64x64 token GEMM body (f32x2) --------------------
#define GEMM_BODY(SRC, W)                                                        \
    ull s2[4][2];                                                                \
    _Pragma("unroll")                                                            \
    for (int i = 0; i < 4; i++) { s2[i][0] = 0ull; s2[i][1] = 0ull; }            \
    for (int kc = 0; kc < 2; kc++) {                                             \
        __syncthreads();                                                         \
        for (int idx = tid; idx < 4096; idx += 256) {                            \
            int r = idx >> 6, kk = idx & 63;                                     \
            As[r * 65 + kk] = SRC[(b * 1024 + n0 + r) * 128 + kc * 64 + kk];     \
            Bs[kk * 66 + r] = W[(j0 + r) * 128 + kc * 64 + kk];                  \
        }                                                                        \
        __syncthreads();                                                         \
        _Pragma("unroll 8")                                                      \
        for (int kk = 0; kk < 64; kk++) {                                        \
            ull b01 = *(const ull*)&Bs[kk * 66 + ty * 4];                        \
            ull b23 = *(const ull*)&Bs[kk * 66 + ty * 4 + 2];                    \
            _Pragma("unroll")                                                    \
            for (int i = 0; i < 4; i++) {                                        \
                ull ad = dup2(As[(i * 16 + tx) * 65 + kk]);                      \
                fma2(s2[i][0], ad, b01);                                         \
                fma2(s2[i][1], ad, b23);                                         \
            }                                                                    \
        }                                                                        \
    }

// ---------------- QKV projection -------------------------------------------
__global__ __launch_bounds__(256) void k_qkv(const float* __restrict__ qkv_w, const float* __restrict__ qkv_b) {
    __shared__ float As[64 * 65];
    __shared__ __align__(16) float Bs[64 * 66];
    int b = blockIdx.z;
    int n0 = blockIdx.x * 64, j0 = blockIdx.y * 64;
    int tx = threadIdx.x, ty = threadIdx.y, tid = ty * 16 + tx;
    GEMM_BODY(g_of, qkv_w)
    const float qs = 0.17677669529663687f * 1.4426950408889634f;
#pragma unroll
    for (int i = 0; i < 4; i++)
#pragma unroll
        for (int pr = 0; pr < 2; pr++) {
            float2 f2 = up2(s2[i][pr]);
            int n = n0 + i * 16 + tx;
#pragma unroll
            for (int lane = 0; lane < 2; lane++) {
                int jj = j0 + ty * 4 + pr * 2 + lane;
                float v = (lane ? f2.y : f2.x) + qkv_b[jj];
                int which = jj >> 7, rem = jj & 127, h = rem >> 5, d = rem & 31;
                if (which == 0)
                    g_q[((b * 4 + h) * 1024 + n) * 32 + d] = v * qs;
                else if (which == 1)
                    g_k[((b * 4 + h) * 1024 + n) * 32 + d] = v;
                else
                    g_v[((b * 4 + h) * 1024 + n) * 32 + d] = v;
            }
        }
}

// ---------------- YV projection --------------------------------------------
__global__ __launch_bounds__(256) void k_yvp(const float* __restrict__ yv_w, const float* __restrict__ yv_b) {
    __shared__ float As[64 * 65];
    __shared__ __align__(16) float Bs[64 * 66];
    int b = blockIdx.z;
    int n0 = blockIdx.x * 64, j0 = blockIdx.y * 64;
    int tx = threadIdx.x, ty = threadIdx.y, tid = ty * 16 + tx;
    GEMM_BODY(g_sn, yv_w)
#pragma unroll
    for (int i = 0; i < 4; i++)
#pragma unroll
        for (int pr = 0; pr < 2; pr++) {
            float2 f2 = up2(s2[i][pr]);
            int n = n0 + i * 16 + tx;
#pragma unroll
            for (int lane = 0; lane < 2; lane++) {
                int jj = j0 + ty * 4 + pr * 2 + lane;
                int h = jj >> 5, d = jj & 31;
                g_yv[((b * 4 + h) * 1024 + n) * 32 + d] = (lane ? f2.y : f2.x) + yv_b[jj];
            }
        }
}

// ---------------- flash attention via tf32 mma ------------------------------
// Block: 128 thr = 4 warps, covers 128 q rows (2 m-tiles per warp).
// KV processed in 32-key tiles. Q pre-scaled by sc*log2e; exp via ex2.
__global__ __launch_bounds__(128) void k_attn() {
    __shared__ float Ksh[32 * 40], Ksl[32 * 40];   // [d][key]
    __shared__ float Vsh[32 * 40], Vsl[32 * 40];   // [key][d]
    __shared__ float Ps[128 * 40];                 // [qrow][key]
    int bh = blockIdx.y;
    int b = bh >> 2, h = bh & 3;
    int q0 = blockIdx.x * 128;
    int tid = threadIdx.x;
    int warp = tid >> 5, lane = tid & 31, g = lane >> 2, t = lane & 3;

    // Q fragments in registers: [m(2)][kc(4)][4 regs], hi + lo
    uint qh[2][4][4], ql[2][4][4];
#pragma unroll
    for (int m = 0; m < 2; m++) {
        int rowg = q0 + m * 64 + warp * 16 + g;
#pragma unroll
        for (int kc = 0; kc < 4; kc++) {
            float v0 = g_q[(bh * 1024 + rowg) * 32 + kc * 8 + t];
            float v1 = g_q[(bh * 1024 + rowg + 8) * 32 + kc * 8 + t];
            float v2 = g_q[(bh * 1024 + rowg) * 32 + kc * 8 + t + 4];
            float v3 = g_q[(bh * 1024 + rowg + 8) * 32 + kc * 8 + t + 4];
            float h0 = tf32hi(v0), h1 = tf32hi(v1), h2 = tf32hi(v2), h3 = tf32hi(v3);
            qh[m][kc][0] = __float_as_uint(h0); ql[m][kc][0] = __float_as_uint(v0 - h0);
            qh[m][kc][1] = __float_as_uint(h1); ql[m][kc][1] = __float_as_uint(v1 - h1);
            qh[m][kc][2] = __float_as_uint(h2); ql[m][kc][2] = __float_as_uint(v2 - h2);
            qh[m][kc][3] = __float_as_uint(h3); ql[m][kc][3] = __float_as_uint(v3 - h3);
        }
    }

    float O[2][4][4];
#pragma unroll
    for (int m = 0; m < 2; m++)
#pragma unroll
        for (int nt = 0; nt < 4; nt++)
#pragma unroll
            for (int r = 0; r < 4; r++) O[m][nt][r] = 0.f;
    float l[2][2] = {{0.f, 0.f}, {0.f, 0.f}};

    for (int ct = 0; ct < 32; ct++) {
        int kb = ct * 32;
        __syncthreads();
        for (int i = tid; i < 1024; i += 128) {
            int key = i >> 5, d = i & 31;
            float kv = g_k[(bh * 1024 + kb + key) * 32 + d];
            float khi = tf32hi(kv);
            Ksh[d * 40 + key] = khi;
            Ksl[d * 40 + key] = kv - khi;
            float vv = g_yv[(bh * 1024 + kb + key) * 32 + d];
            float vhi = tf32hi(vv);
            Vsh[key * 40 + d] = vhi;
            Vsl[key * 40 + d] = vv - vhi;
        }
        __syncthreads();

        // S = Q K^T  (split-tf32: hh + lh + hl)
        float s[2][4][4];
#pragma unroll
        for (int m = 0; m < 2; m++)
#pragma unroll
            for (int nt = 0; nt < 4; nt++)
#pragma unroll
                for (int r = 0; r < 4; r++) s[m][nt][r] = 0.f;
#pragma unroll
        for (int kc = 0; kc < 4; kc++) {
#pragma unroll
            for (int nt = 0; nt < 4; nt++) {
                int col = nt * 8 + g;
                uint bh0 = __float_as_uint(Ksh[(kc * 8 + t) * 40 + col]);
                uint bh1 = __float_as_uint(Ksh[(kc * 8 + t + 4) * 40 + col]);
                uint bl0 = __float_as_uint(Ksl[(kc * 8 + t) * 40 + col]);
                uint bl1 = __float_as_uint(Ksl[(kc * 8 + t + 4) * 40 + col]);
#pragma unroll
                for (int m = 0; m < 2; m++) {
                    mma_tf32(s[m][nt], qh[m][kc], bh0, bh1);
                    mma_tf32(s[m][nt], ql[m][kc], bh0, bh1);
                    mma_tf32(s[m][nt], qh[m][kc], bl0, bl1);
                }
            }
        }
        // exp (base-2, scale pre-folded into Q), stage P, accumulate l
#pragma unroll
        for (int m = 0; m < 2; m++) {
            int rowg = m * 64 + warp * 16 + g;
#pragma unroll
            for (int nt = 0; nt < 4; nt++) {
                float p0 = ex2(s[m][nt][0]);
                float p1 = ex2(s[m][nt][1]);
                float p2 = ex2(s[m][nt][2]);
                float p3 = ex2(s[m][nt][3]);
                *(float2*)&Ps[rowg * 40 + nt * 8 + 2 * t]       = make_float2(p0, p1);
                *(float2*)&Ps[(rowg + 8) * 40 + nt * 8 + 2 * t] = make_float2(p2, p3);
                l[m][0] += p0 + p1;
                l[m][1] += p2 + p3;
            }
        }
        __syncwarp();
        // O += P V  (Ph*Vh + Ph*Vl)
#pragma unroll
        for (int kc = 0; kc < 4; kc++) {
            uint ap[2][4];
#pragma unroll
            for (int m = 0; m < 2; m++) {
                int rowg = m * 64 + warp * 16 + g;
                ap[m][0] = __float_as_uint(tf32hi(Ps[rowg * 40 + kc * 8 + t]));
                ap[m][1] = __float_as_uint(tf32hi(Ps[(rowg + 8) * 40 + kc * 8 + t]));
                ap[m][2] = __float_as_uint(tf32hi(Ps[rowg * 40 + kc * 8 + t + 4]));
                ap[m][3] = __float_as_uint(tf32hi(Ps[(rowg + 8) * 40 + kc * 8 + t + 4]));
            }
#pragma unroll
            for (int nt = 0; nt < 4; nt++) {
                int col = nt * 8 + g;
                uint bh0 = __float_as_uint(Vsh[(kc * 8 + t) * 40 + col]);
                uint bh1 = __float_as_uint(Vsh[(kc * 8 + t + 4) * 40 + col]);
                uint bl0 = __float_as_uint(Vsl[(kc * 8 + t) * 40 + col]);
                uint bl1 = __float_as_uint(Vsl[(kc * 8 + t + 4) * 40 + col]);
#pragma unroll
                for (int m = 0; m < 2; m++) {
                    mma_tf32(O[m][nt], ap[m], bh0, bh1);
                    mma_tf32(O[m][nt], ap[m], bl0, bl1);
                }
            }
        }
        __syncwarp();
    }

    // reduce l across the quad (t lanes), then write out
#pragma unroll
    for (int m = 0; m < 2; m++)
#pragma unroll
        for (int r = 0; r < 2; r++) {
            l[m][r] += __shfl_xor_sync(0xffffffffu, l[m][r], 1);
            l[m][r] += __shfl_xor_sync(0xffffffffu, l[m][r], 2);
        }
#pragma unroll
    for (int m = 0; m < 2; m++) {
        int rowg = q0 + m * 64 + warp * 16 + g;
        float inv0 = 1.f / l[m][0];
        float inv1 = 1.f / l[m][1];
#pragma unroll
        for (int nt = 0; nt < 4; nt++) {
            int d0 = nt * 8 + 2 * t;
            float o0 = g_v[(bh * 1024 + rowg) * 32 + d0]     + O[m][nt][0] * inv0;
            float o1 = g_v[(bh * 1024 + rowg) * 32 + d0 + 1] + O[m][nt][1] * inv0;
            *(float2*)&g_xv[(b * 1024 + rowg) * 128 + h * 32 + d0] = make_float2(o0, o1);
            float o2 = g_v[(bh * 1024 + rowg + 8) * 32 + d0]     + O[m][nt][2] * inv1;
            float o3 = g_v[(bh * 1024 + rowg + 8) * 32 + d0 + 1] + O[m][nt][3] * inv1;
            *(float2*)&g_xv[(b * 1024 + rowg + 8) * 128 + h * 32 + d0] = make_float2(o2, o3);
        }
    }
}

// ---------------- output proj + residual, transposed store -----------------
__global__ __launch_bounds__(256) void k_proj(const float* __restrict__ proj_w, const float* __restrict__ proj_b) {
    __shared__ float As[64 * 65];
    __shared__ __align__(16) float Bs[64 * 66];
    int b = blockIdx.z;
    int n0 = blockIdx.x * 64, j0 = blockIdx.y * 64;
    int tx = threadIdx.x, ty = threadIdx.y, tid = ty * 16 + tx;
    GEMM_BODY(g_xv, proj_w)
#pragma unroll
    for (int i = 0; i < 4; i++)
#pragma unroll
        for (int pr = 0; pr < 2; pr++) {
            float2 f2 = up2(s2[i][pr]);
            int n = n0 + i * 16 + tx;
#pragma unroll
            for (int lane = 0; lane < 2; lane++) {
                int jj = j0 + ty * 4 + pr * 2 + lane;
                float v = (lane ? f2.y : f2.x) + proj_b[jj] + g_ori[(b * 1024 + n) * 128 + jj];
                g_x2[(b * 128 + jj) * 1024 + n] = v;
            }
        }
}

// ---------------- token conv1d (f32x2) + residual --------------------------
__global__ __launch_bounds__(256) void k_conv1d() {
    __shared__ __align__(16) float Xs[32 * 132];
    __shared__ __align__(16) float Ws[32 * 64];
    int b = blockIdx.z, co0 = blockIdx.y * 64, n0 = blockIdx.x * 128;
    int tx = threadIdx.x, ty = threadIdx.y, tid = ty * 32 + tx;

    ull acc[4][4];
#pragma unroll
    for (int p = 0; p < 4; p++)
#pragma unroll
        for (int j = 0; j < 4; j++) acc[p][j] = 0ull;

    for (int cc = 0; cc < 4; cc++) {
        __syncthreads();
        for (int idx = tid; idx < 4224; idx += 256) {
            int cil = idx / 132, t = idx % 132;
            int n = n0 - 2 + t;
            Xs[idx] = (n >= 0 && n < 1024) ? g_x2[(b * 128 + cc * 32 + cil) * 1024 + n] : 0.f;
        }
        for (int k = 0; k < 5; k++) {
            __syncthreads();
            {
                int base = (k * 128 + cc * 32) * 128 + co0;
                for (int idx = tid; idx < 2048; idx += 256) {
                    int cil = idx >> 6, col = idx & 63;
                    Ws[cil * 64 + col] = g_wc1[base + cil * 128 + col];
                }
            }
            __syncthreads();
#pragma unroll 4
            for (int cil = 0; cil < 32; cil++) {
                ulonglong2 wA = *(const ulonglong2*)&Ws[cil * 64 + ty * 8];
                ulonglong2 wB = *(const ulonglong2*)&Ws[cil * 64 + ty * 8 + 4];
                ull wp[4] = {wA.x, wA.y, wB.x, wB.y};
                ull xd[4];
#pragma unroll
                for (int j = 0; j < 4; j++)
                    xd[j] = dup2(Xs[cil * 132 + tx + 32 * j + k]);
#pragma unroll
                for (int p = 0; p < 4; p++)
#pragma unroll
                    for (int j = 0; j < 4; j++) fma2(acc[p][j], wp[p], xd[j]);
            }
        }
        __syncthreads();
    }
#pragma unroll
    for (int p = 0; p < 4; p++)
#pragma unroll
        for (int lane = 0; lane < 2; lane++) {
            int co = co0 + ty * 8 + p * 2 + lane;
#pragma unroll
            for (int j = 0; j < 4; j++) {
                float2 f2 = up2(acc[p][j]);
                int n = n0 + tx + 32 * j;
                g_y2[(b * 128 + co) * 1024 + n] =
                    (lane ? f2.y : f2.x) + g_x2[(b * 128 + co) * 1024 + n];
            }
        }
}

// ---------------- bilinear 32->96 upsample (align_corners) -----------------
__global__ void k_up(float* __restrict__ out) {
    int j = threadIdx.x;
    int i = blockIdx.x * 4 + threadIdx.y;
    int c = blockIdx.y, b = blockIdx.z;
    const float sc = 31.0f / 95.0f;
    float cy = (float)i * sc;
    int i0 = (int)cy;
    float wy = cy - (float)i0;
    int i1 = min(i0 + 1, 31);
    float cx = (float)j * sc;
    int j0 = (int)cx;
    float wx = cx - (float)j0;
    int j1 = min(j0 + 1, 31);
    const float* Y = &g_y2[(b * 128 + c) * 1024];
    float v00 = Y[i0 * 32 + j0], v10 = Y[i1 * 32 + j0];
    float v01 = Y[i0 * 32 + j1], v11 = Y[i1 * 32 + j1];
    float a0 = v00 * (1.f - wy) + v10 * wy;
    float a1 = v01 * (1.f - wy) + v11 * wy;
    out[((b * 128 + c) * 96 + i) * 96 + j] = a0 * (1.f - wx) + a1 * wx;
}

// ---------------- launch ----------------------------------------------------
extern "C" void kernel_launch(void* const* d_in, const int* in_sizes, int n_in,
                              void* d_out, int out_size) {
    const float* s1     = (const float*)d_in[0];
    const float* o      = (const float*)d_in[1];
    const int*   index  = (const int*)  d_in[2];
    const float* pe_w   = (const float*)d_in[3];
    const float* bn_g   = (const float*)d_in[4];
    const float* bn_b   = (const float*)d_in[5];
    const float* bn_m   = (const float*)d_in[6];
    const float* bn_v   = (const float*)d_in[7];
    const float* lnx_g  = (const float*)d_in[8];
    const float* lnx_b  = (const float*)d_in[9];
    const float* lny_g  = (const float*)d_in[10];
    const float* lny_b  = (const float*)d_in[11];
    const float* qkv_w  = (const float*)d_in[12];
    const float* qkv_b  = (const float*)d_in[13];
    const float* yv_w   = (const float*)d_in[14];
    const float* yv_b   = (const float*)d_in[15];
    const float* proj_w = (const float*)d_in[16];
    const float* proj_b = (const float*)d_in[17];
    const float* c1d_w  = (const float*)d_in[18];
    float* out = (float*)d_out;

    k_repack    <<<320, 256>>>(pe_w, c1d_w);
    k_transpose <<<dim3(3, 96, 64), dim3(32, 32)>>>(s1);
    k_peconv    <<<dim3(144, 16), 256>>>(index, bn_g, bn_b, bn_m, bn_v);
    k_pool_short<<<dim3(1024, 16), 128>>>(lny_g, lny_b);
    k_pool_o    <<<dim3(32, 4, 16), 256>>>(o);
    k_ln_of     <<<dim3(1024, 16), 128>>>(lnx_g, lnx_b);
    k_qkv       <<<dim3(16, 6, 16), dim3(16, 16)>>>(qkv_w, qkv_b);
    k_yvp       <<<dim3(16, 2, 16), dim3(16, 16)>>>(yv_w, yv_b);
    k_attn      <<<dim3(8, 64), 128>>>();
    k_proj      <<<dim3(16, 2, 16), dim3(16, 16)>>>(proj_w, proj_b);
    k_conv1d    <<<dim3(8, 2, 16), dim3(32, 8)>>>();
    k_up        <<<dim3(24, 128, 16), dim3(96, 4)>>>(out);
}

// round 6
// speedup vs baseline: 1.5225x; 1.1100x over previous
#include <cuda_runtime.h>
#include <cuda_bf16.h>

typedef unsigned long long ull;
typedef unsigned int uint;
typedef unsigned short ushort;

// ---------------- helpers ---------------------------------------------------
__device__ __forceinline__ void fma2(ull& d, ull a, ull b) {
    asm("fma.rn.f32x2 %0, %1, %2, %0;" : "+l"(d) : "l"(a), "l"(b));
}
__device__ __forceinline__ ull dup2(float x) {
    ull r; asm("mov.b64 %0, {%1, %1};" : "=l"(r) : "f"(x)); return r;
}
__device__ __forceinline__ float2 up2(ull v) {
    float2 f; asm("mov.b64 {%0, %1}, %2;" : "=f"(f.x), "=f"(f.y) : "l"(v)); return f;
}
__device__ __forceinline__ float ex2(float x) {
    float r; asm("ex2.approx.ftz.f32 %0, %1;" : "=f"(r) : "f"(x)); return r;
}
__device__ __forceinline__ float tf32hi(float x) {
    uint u; asm("cvt.rna.tf32.f32 %0, %1;" : "=r"(u) : "f"(x));
    return __uint_as_float(u);
}
__device__ __forceinline__ void mma_tf32(float* c, const uint* a, uint b0, uint b1) {
    asm volatile(
        "mma.sync.aligned.m16n8k8.row.col.f32.tf32.tf32.f32 "
        "{%0,%1,%2,%3}, {%4,%5,%6,%7}, {%8,%9}, {%0,%1,%2,%3};"
        : "+f"(c[0]), "+f"(c[1]), "+f"(c[2]), "+f"(c[3])
        : "r"(a[0]), "r"(a[1]), "r"(a[2]), "r"(a[3]), "r"(b0), "r"(b1));
}
__device__ __forceinline__ void mma_bf16(float* c, const uint* a, uint b0, uint b1) {
    asm volatile(
        "mma.sync.aligned.m16n8k16.row.col.f32.bf16.bf16.f32 "
        "{%0,%1,%2,%3}, {%4,%5,%6,%7}, {%8,%9}, {%0,%1,%2,%3};"
        : "+f"(c[0]), "+f"(c[1]), "+f"(c[2]), "+f"(c[3])
        : "r"(a[0]), "r"(a[1]), "r"(a[2]), "r"(a[3]), "r"(b0), "r"(b1));
}
__device__ __forceinline__ void bsplit(float v, ushort& h, ushort& m) {
    __nv_bfloat16 bh = __float2bfloat16_rn(v);
    float r = v - __bfloat162float(bh);
    __nv_bfloat16 bm = __float2bfloat16_rn(r);
    h = __bfloat16_as_ushort(bh);
    m = __bfloat16_as_ushort(bm);
}

// ---------------- scratch (device globals; no allocations) ----------------
__device__ float g_x   [18874368];   // [16][64][18432] patch-major im2col of s1
__device__ float g_z   [18874368];   // conv+bn+relu+mask output
__device__ float g_ori [2097152];    // [16][1024][128] pooled short tokens
__device__ float g_sn  [2097152];    // LN(ori)
__device__ float g_ofr [2097152];    // pooled o tokens (raw)
__device__ float g_of  [2097152];    // LN(of)
__device__ float g_q   [2097152];    // [16][4][1024][32]  (pre-scaled by sc*log2e)
__device__ float g_k   [2097152];
__device__ float g_v   [2097152];
__device__ float g_yv  [2097152];
__device__ float g_xv  [2097152];    // [16][1024][128]
__device__ float g_x2  [2097152];    // [16][128][1024]
__device__ float g_y2  [2097152];    // conv1d output
__device__ uint  g_peA_h[10240];     // pe weights, m16n8k16 A-frag packed bf16x2 (hi)
__device__ uint  g_peA_m[10240];     // mid plane
__device__ uint  g_c1A_h[40960];     // conv1d weights, A-frag packed (hi)
__device__ uint  g_c1A_m[40960];

// ---------------- L1: transpose + weight packs ------------------------------
// blockIdx.x 0..2: s1 transpose; blockIdx.x==3: weight fragment packing.
__global__ void k_pre(const float* __restrict__ s1,
                      const float* __restrict__ pe_w,
                      const float* __restrict__ c1d_w) {
    int tx = threadIdx.x, ty = threadIdx.y;
    if (blockIdx.x < 3) {
        __shared__ float tbuf[32][33];
        int b = blockIdx.z >> 2, cg = blockIdx.z & 3;
        int row = blockIdx.y;
        int W0 = blockIdx.x * 32;
        tbuf[ty][tx] = s1[((b * 128 + cg * 32 + ty) * 96 + row) * 96 + W0 + tx];
        __syncthreads();
        int Wl = W0 + ty;
        int w = Wl / 12, p2 = Wl % 12;
        int h = row / 12, p1 = row % 12;
        g_x[(b * 64 + h * 8 + w) * 18432 + (p1 * 12 + p2) * 128 + cg * 32 + tx] = tbuf[tx][ty];
        return;
    }
    int bidx = blockIdx.y * 64 + blockIdx.z;
    if (bidx >= 50) return;
    int id = bidx * 1024 + ty * 32 + tx;
    if (id < 10240) {
        // pe pack: [chunk20][mt4][lane32][r4], chunk = kk*4 + pc
        int r = id & 3, lane = (id >> 2) & 31, mt = (id >> 7) & 3, ch = id >> 9;
        int kk = ch >> 2, pc = ch & 3, g = lane >> 2, t = lane & 3;
        int po = mt * 16 + g + 8 * (r & 1);
        int k0 = 2 * t + 8 * (r >> 1);
        int pi0 = pc * 16 + k0;
        float w0 = pe_w[(po * 64 + pi0) * 5 + kk];
        float w1 = pe_w[(po * 64 + pi0 + 1) * 5 + kk];
        ushort h0, m0, h1, m1;
        bsplit(w0, h0, m0); bsplit(w1, h1, m1);
        g_peA_h[id] = ((uint)h1 << 16) | h0;
        g_peA_m[id] = ((uint)m1 << 16) | m0;
    } else if (id < 51200) {
        // c1d pack: [chunk40][mt8][lane32][r4], chunk = kk*8 + cic
        int e = id - 10240;
        int r = e & 3, lane = (e >> 2) & 31, mt = (e >> 7) & 7, ch = e >> 10;
        int kk = ch >> 3, cic = ch & 7, g = lane >> 2, t = lane & 3;
        int co = mt * 16 + g + 8 * (r & 1);
        int k0 = 2 * t + 8 * (r >> 1);
        int ci0 = cic * 16 + k0;
        float w0 = c1d_w[(co * 128 + ci0) * 5 + kk];
        float w1 = c1d_w[(co * 128 + ci0 + 1) * 5 + kk];
        ushort h0, m0, h1, m1;
        bsplit(w0, h0, m0); bsplit(w1, h1, m1);
        g_c1A_h[e] = ((uint)h1 << 16) | h0;
        g_c1A_m[e] = ((uint)m1 << 16) | m0;
    }
}

// ---------------- L2: patch-embed conv via bf16x3 mma + BN + ReLU + mask ---
// Block: (f-tile 128, b). 8 warps; warp w owns n8 tiles {2w, 2w+1}, all 4 m-tiles.
__global__ __launch_bounds__(256) void k_peconv(
    const int* __restrict__ index,
    const float* __restrict__ bn_g, const float* __restrict__ bn_b,
    const float* __restrict__ bn_m, const float* __restrict__ bn_v) {
    __shared__ uint Xph[32 * 136];   // [pi-pair][halo col], bf16x2 (rows 2p, 2p+1)
    __shared__ uint Xpm[32 * 136];
    int b = blockIdx.y;
    int f0 = blockIdx.x * 128;
    int tid = threadIdx.x;
    int w = tid >> 5, lane = tid & 31, g = lane >> 2, t = lane & 3;

    // stage X split into bf16 hi/mid pair-packed planes
    for (int it = tid; it < 32 * 132; it += 256) {
        int pr = it / 132, col = it % 132;
        int f = f0 - 2 + col;
        float v0 = 0.f, v1 = 0.f;
        if (f >= 0 && f < 18432) {
            v0 = g_x[(b * 64 + 2 * pr) * 18432 + f];
            v1 = g_x[(b * 64 + 2 * pr + 1) * 18432 + f];
        }
        ushort h0, m0, h1, m1;
        bsplit(v0, h0, m0); bsplit(v1, h1, m1);
        Xph[pr * 136 + col] = ((uint)h1 << 16) | h0;
        Xpm[pr * 136 + col] = ((uint)m1 << 16) | m0;
    }
    __syncthreads();

    float acc[2][4][4];
#pragma unroll
    for (int n = 0; n < 2; n++)
#pragma unroll
        for (int m = 0; m < 4; m++)
#pragma unroll
            for (int r = 0; r < 4; r++) acc[n][m][r] = 0.f;

    for (int c = 0; c < 20; c++) {
        int kk = c >> 2, pc = c & 3;
        uint bh[2][2], bm[2][2];
#pragma unroll
        for (int ntl = 0; ntl < 2; ntl++) {
            int coln = (w * 2 + ntl) * 8 + g + kk;
            int rb = (pc * 8 + t) * 136 + coln;
            bh[ntl][0] = Xph[rb];
            bh[ntl][1] = Xph[rb + 4 * 136];
            bm[ntl][0] = Xpm[rb];
            bm[ntl][1] = Xpm[rb + 4 * 136];
        }
#pragma unroll
        for (int mt = 0; mt < 4; mt++) {
            uint4 a4h = *(const uint4*)&g_peA_h[((c * 4 + mt) * 32 + lane) * 4];
            uint4 a4m = *(const uint4*)&g_peA_m[((c * 4 + mt) * 32 + lane) * 4];
            uint ah[4] = {a4h.x, a4h.y, a4h.z, a4h.w};
            uint am[4] = {a4m.x, a4m.y, a4m.z, a4m.w};
#pragma unroll
            for (int ntl = 0; ntl < 2; ntl++) {
                mma_bf16(acc[ntl][mt], ah, bh[ntl][0], bh[ntl][1]);
                mma_bf16(acc[ntl][mt], am, bh[ntl][0], bh[ntl][1]);
                mma_bf16(acc[ntl][mt], ah, bm[ntl][0], bm[ntl][1]);
            }
        }
    }

    int pidx0 = (index[0] / 12) * 8 + index[1] / 12;
    int pidx1 = (index[2] / 12) * 8 + index[3] / 12;
    int pidx2 = (index[4] / 12) * 8 + index[5] / 12;
    int pidx3 = (index[6] / 12) * 8 + index[7] / 12;

#pragma unroll
    for (int mt = 0; mt < 4; mt++) {
        int poA = mt * 16 + g, poB = poA + 8;
        bool selA = (poA == pidx0) | (poA == pidx1) | (poA == pidx2) | (poA == pidx3);
        bool selB = (poB == pidx0) | (poB == pidx1) | (poB == pidx2) | (poB == pidx3);
        float mA = bn_m[poA], sA = rsqrtf(bn_v[poA] + 1e-5f), gA = bn_g[poA], bA = bn_b[poA];
        float mB = bn_m[poB], sB = rsqrtf(bn_v[poB] + 1e-5f), gB = bn_g[poB], bB = bn_b[poB];
#pragma unroll
        for (int ntl = 0; ntl < 2; ntl++) {
            int f = f0 + (w * 2 + ntl) * 8 + 2 * t;
            float v0 = fmaxf((acc[ntl][mt][0] - mA) * sA * gA + bA, 0.f);
            float v1 = fmaxf((acc[ntl][mt][1] - mA) * sA * gA + bA, 0.f);
            if (!selA) { v0 *= v0; v1 *= v1; }
            *(float2*)&g_z[(b * 64 + poA) * 18432 + f] = make_float2(v0, v1);
            float v2 = fmaxf((acc[ntl][mt][2] - mB) * sB * gB + bB, 0.f);
            float v3 = fmaxf((acc[ntl][mt][3] - mB) * sB * gB + bB, 0.f);
            if (!selB) { v2 *= v2; v3 *= v3; }
            *(float2*)&g_z[(b * 64 + poB) * 18432 + f] = make_float2(v2, v3);
        }
    }
}

// ---------------- LN helper (blockDim.x == 128) ----------------------------
__device__ __forceinline__ void ln_stats128(float v, float& mean, float& rstd) {
    float s = v, s2 = v * v;
#pragma unroll
    for (int off = 16; off; off >>= 1) {
        s  += __shfl_xor_sync(0xffffffffu, s,  off);
        s2 += __shfl_xor_sync(0xffffffffu, s2, off);
    }
    __shared__ float sm[4], sm2[4];
    int w = threadIdx.x >> 5, ln = threadIdx.x & 31;
    if (ln == 0) { sm[w] = s; sm2[w] = s2; }
    __syncthreads();
    s  = sm[0] + sm[1] + sm[2] + sm[3];
    s2 = sm2[0] + sm2[1] + sm2[2] + sm2[3];
    mean = s * (1.f / 128.f);
    float var = s2 * (1.f / 128.f) - mean * mean;
    rstd = rsqrtf(var + 1e-5f);
}

// ---------------- L3: 3x3 pool of z -> ori + LN -> sn ----------------------
__global__ void k_pool_short(const float* __restrict__ lny_g, const float* __restrict__ lny_b) {
    int n = blockIdx.x, b = blockIdx.y, c = threadIdx.x;
    int oh = n >> 5, ow = n & 31;
    int p = (oh >> 2) * 8 + (ow >> 2);
    int base = (b * 64 + p) * 18432;
    int p1s = (oh & 3) * 3, p2s = (ow & 3) * 3;
    float s = 0.f;
#pragma unroll
    for (int r = 0; r < 3; r++)
#pragma unroll
        for (int t = 0; t < 3; t++)
            s += g_z[base + ((p1s + r) * 12 + p2s + t) * 128 + c];
    s *= (1.f / 9.f);
    g_ori[(b * 1024 + n) * 128 + c] = s;
    float mean, rstd;
    ln_stats128(s, mean, rstd);
    g_sn[(b * 1024 + n) * 128 + c] = (s - mean) * rstd * lny_g[c] + lny_b[c];
}

// ---------------- L4: 2x2 pool of o + LN (fused) ---------------------------
__global__ void k_pool_o_ln(const float* __restrict__ o,
                            const float* __restrict__ lnx_g, const float* __restrict__ lnx_b) {
    __shared__ float S[32 * 129];
    int oh = blockIdx.x, b = blockIdx.y;
    int tid = threadIdx.x;
#pragma unroll
    for (int it = 0; it < 16; it++) {
        int idx = it * 256 + tid;
        int c = idx >> 5, ow = idx & 31;
        const float* p = &o[((b * 128 + c) * 64 + 2 * oh) * 64 + 2 * ow];
        S[ow * 129 + c] = 0.25f * (p[0] + p[1] + p[64] + p[65]);
    }
    __syncthreads();
    int warp = tid >> 5, ln = tid & 31;
#pragma unroll
    for (int i = 0; i < 4; i++) {
        int ow = warp * 4 + i;
        float v[4];
        float s = 0.f, s2 = 0.f;
#pragma unroll
        for (int j = 0; j < 4; j++) {
            v[j] = S[ow * 129 + j * 32 + ln];
            s += v[j]; s2 += v[j] * v[j];
        }
#pragma unroll
        for (int off = 16; off; off >>= 1) {
            s  += __shfl_xor_sync(0xffffffffu, s,  off);
            s2 += __shfl_xor_sync(0xffffffffu, s2, off);
        }
        float mean = s * (1.f / 128.f);
        float rstd = rsqrtf(s2 * (1.f / 128.f) - mean * mean + 1e-5f);
        int n = oh * 32 + ow;
#pragma unroll
        for (int j = 0; j < 4; j++) {
            int c = j * 32 + ln;
            g_ofr[(b * 1024 + n) * 128 + c] = v[j];
            g_of [(b * 1024 + n) * 128 + c] = (v[j] - mean) * rstd * lnx_g[c] + lnx_b[c];
        }
    }
}

// ---------------- L5: fused QKV + YV projections (f32x2 GEMM) --------------
__global__ __launch_bounds__(256) void k_qkv_yv(
    const float* __restrict__ qkv_w, const float* __restrict__ qkv_b,
    const float* __restrict__ yv_w,  const float* __restrict__ yv_b) {
    __shared__ float As[64 * 65];
    __shared__ __align__(16) float Bs[64 * 66];
    int b = blockIdx.z;
    int n0 = blockIdx.x * 64;
    int y = blockIdx.y;
    bool isq = y < 6;
    int j0 = isq ? y * 64 : (y - 6) * 64;
    const float* SRC  = isq ? g_of  : g_sn;
    const float* W    = isq ? qkv_w : yv_w;
    const float* bias = isq ? qkv_b : yv_b;
    int tx = threadIdx.x, ty = threadIdx.y, tid = ty * 16 + tx;

    ull s2[4][2];
#pragma unroll
    for (int i = 0; i < 4; i++) { s2[i][0] = 0ull; s2[i][1] = 0ull; }
    for (int kc = 0; kc < 2; kc++) {
        __syncthreads();
        for (int idx = tid; idx < 4096; idx += 256) {
            int r = idx >> 6, kk = idx & 63;
            As[r * 65 + kk] = SRC[(b * 1024 + n0 + r) * 128 + kc * 64 + kk];
            Bs[kk * 66 + r] = W[(j0 + r) * 128 + kc * 64 + kk];
        }
        __syncthreads();
#pragma unroll 8
        for (int kk = 0; kk < 64; kk++) {
            ull b01 = *(const ull*)&Bs[kk * 66 + ty * 4];
            ull b23 = *(const ull*)&Bs[kk * 66 + ty * 4 + 2];
#pragma unroll
            for (int i = 0; i < 4; i++) {
                ull ad = dup2(As[(i * 16 + tx) * 65 + kk]);
                fma2(s2[i][0], ad, b01);
                fma2(s2[i][1], ad, b23);
            }
        }
    }
    const float qs = 0.17677669529663687f * 1.4426950408889634f;
#pragma unroll
    for (int i = 0; i < 4; i++)
#pragma unroll
        for (int pr = 0; pr < 2; pr++) {
            float2 f2 = up2(s2[i][pr]);
            int n = n0 + i * 16 + tx;
#pragma unroll
            for (int lane = 0; lane < 2; lane++) {
                int jj = j0 + ty * 4 + pr * 2 + lane;
                float v = (lane ? f2.y : f2.x) + bias[jj];
                if (isq) {
                    int which = jj >> 7, rem = jj & 127, h = rem >> 5, d = rem & 31;
                    if (which == 0)
                        g_q[((b * 4 + h) * 1024 + n) * 32 + d] = v * qs;
                    else if (which == 1)
                        g_k[((b * 4 + h) * 1024 + n) * 32 + d] = v;
                    else
                        g_v[((b * 4 + h) * 1024 + n) * 32 + d] = v;
                } else {
                    int h = jj >> 5, d = jj & 31;
                    g_yv[((b * 4 + h) * 1024 + n) * 32 + d] = v;
                }
            }
        }
}

// ---------------- L6: flash attention via tf32 mma (PROFILED SLOT) ---------
__global__ __launch_bounds__(128) void k_attn() {
    __shared__ float Ksh[32 * 40], Ksl[32 * 40];   // [d][key]
    __shared__ float Vsh[32 * 40], Vsl[32 * 40];   // [key][d]
    __shared__ float Ps[128 * 40];                 // [qrow][key]
    int bh = blockIdx.y;
    int b = bh >> 2, h = bh & 3;
    int q0 = blockIdx.x * 128;
    int tid = threadIdx.x;
    int warp = tid >> 5, lane = tid & 31, g = lane >> 2, t = lane & 3;

    uint qh[2][4][4], ql[2][4][4];
#pragma unroll
    for (int m = 0; m < 2; m++) {
        int rowg = q0 + m * 64 + warp * 16 + g;
#pragma unroll
        for (int kc = 0; kc < 4; kc++) {
            float v0 = g_q[(bh * 1024 + rowg) * 32 + kc * 8 + t];
            float v1 = g_q[(bh * 1024 + rowg + 8) * 32 + kc * 8 + t];
            float v2 = g_q[(bh * 1024 + rowg) * 32 + kc * 8 + t + 4];
            float v3 = g_q[(bh * 1024 + rowg + 8) * 32 + kc * 8 + t + 4];
            float h0 = tf32hi(v0), h1 = tf32hi(v1), h2 = tf32hi(v2), h3 = tf32hi(v3);
            qh[m][kc][0] = __float_as_uint(h0); ql[m][kc][0] = __float_as_uint(v0 - h0);
            qh[m][kc][1] = __float_as_uint(h1); ql[m][kc][1] = __float_as_uint(v1 - h1);
            qh[m][kc][2] = __float_as_uint(h2); ql[m][kc][2] = __float_as_uint(v2 - h2);
            qh[m][kc][3] = __float_as_uint(h3); ql[m][kc][3] = __float_as_uint(v3 - h3);
        }
    }

    float O[2][4][4];
#pragma unroll
    for (int m = 0; m < 2; m++)
#pragma unroll
        for (int nt = 0; nt < 4; nt++)
#pragma unroll
            for (int r = 0; r < 4; r++) O[m][nt][r] = 0.f;
    float l[2][2] = {{0.f, 0.f}, {0.f, 0.f}};

    for (int ct = 0; ct < 32; ct++) {
        int kb = ct * 32;
        __syncthreads();
        for (int i = tid; i < 1024; i += 128) {
            int key = i >> 5, d = i & 31;
            float kv = g_k[(bh * 1024 + kb + key) * 32 + d];
            float khi = tf32hi(kv);
            Ksh[d * 40 + key] = khi;
            Ksl[d * 40 + key] = kv - khi;
            float vv = g_yv[(bh * 1024 + kb + key) * 32 + d];
            float vhi = tf32hi(vv);
            Vsh[key * 40 + d] = vhi;
            Vsl[key * 40 + d] = vv - vhi;
        }
        __syncthreads();

        float s[2][4][4];
#pragma unroll
        for (int m = 0; m < 2; m++)
#pragma unroll
            for (int nt = 0; nt < 4; nt++)
#pragma unroll
                for (int r = 0; r < 4; r++) s[m][nt][r] = 0.f;
#pragma unroll
        for (int kc = 0; kc < 4; kc++) {
#pragma unroll
            for (int nt = 0; nt < 4; nt++) {
                int col = nt * 8 + g;
                uint bh0 = __float_as_uint(Ksh[(kc * 8 + t) * 40 + col]);
                uint bh1 = __float_as_uint(Ksh[(kc * 8 + t + 4) * 40 + col]);
                uint bl0 = __float_as_uint(Ksl[(kc * 8 + t) * 40 + col]);
                uint bl1 = __float_as_uint(Ksl[(kc * 8 + t + 4) * 40 + col]);
#pragma unroll
                for (int m = 0; m < 2; m++) {
                    mma_tf32(s[m][nt], qh[m][kc], bh0, bh1);
                    mma_tf32(s[m][nt], ql[m][kc], bh0, bh1);
                    mma_tf32(s[m][nt], qh[m][kc], bl0, bl1);
                }
            }
        }
#pragma unroll
        for (int m = 0; m < 2; m++) {
            int rowg = m * 64 + warp * 16 + g;
#pragma unroll
            for (int nt = 0; nt < 4; nt++) {
                float p0 = ex2(s[m][nt][0]);
                float p1 = ex2(s[m][nt][1]);
                float p2 = ex2(s[m][nt][2]);
                float p3 = ex2(s[m][nt][3]);
                *(float2*)&Ps[rowg * 40 + nt * 8 + 2 * t]       = make_float2(p0, p1);
                *(float2*)&Ps[(rowg + 8) * 40 + nt * 8 + 2 * t] = make_float2(p2, p3);
                l[m][0] += p0 + p1;
                l[m][1] += p2 + p3;
            }
        }
        __syncwarp();
#pragma unroll
        for (int kc = 0; kc < 4; kc++) {
            uint ap[2][4];
#pragma unroll
            for (int m = 0; m < 2; m++) {
                int rowg = m * 64 + warp * 16 + g;
                ap[m][0] = __float_as_uint(tf32hi(Ps[rowg * 40 + kc * 8 + t]));
                ap[m][1] = __float_as_uint(tf32hi(Ps[(rowg + 8) * 40 + kc * 8 + t]));
                ap[m][2] = __float_as_uint(tf32hi(Ps[rowg * 40 + kc * 8 + t + 4]));
                ap[m][3] = __float_as_uint(tf32hi(Ps[(rowg + 8) * 40 + kc * 8 + t + 4]));
            }
#pragma unroll
            for (int nt = 0; nt < 4; nt++) {
                int col = nt * 8 + g;
                uint bh0 = __float_as_uint(Vsh[(kc * 8 + t) * 40 + col]);
                uint bh1 = __float_as_uint(Vsh[(kc * 8 + t + 4) * 40 + col]);
                uint bl0 = __float_as_uint(Vsl[(kc * 8 + t) * 40 + col]);
                uint bl1 = __float_as_uint(Vsl[(kc * 8 + t + 4) * 40 + col]);
#pragma unroll
                for (int m = 0; m < 2; m++) {
                    mma_tf32(O[m][nt], ap[m], bh0, bh1);
                    mma_tf32(O[m][nt], ap[m], bl0, bl1);
                }
            }
        }
        __syncwarp();
    }

#pragma unroll
    for (int m = 0; m < 2; m++)
#pragma unroll
        for (int r = 0; r < 2; r++) {
            l[m][r] += __shfl_xor_sync(0xffffffffu, l[m][r], 1);
            l[m][r] += __shfl_xor_sync(0xffffffffu, l[m][r], 2);
        }
#pragma unroll
    for (int m = 0; m < 2; m++) {
        int rowg = q0 + m * 64 + warp * 16 + g;
        float inv0 = 1.f / l[m][0];
        float inv1 = 1.f / l[m][1];
#pragma unroll
        for (int nt = 0; nt < 4; nt++) {
            int d0 = nt * 8 + 2 * t;
            float o0 = g_v[(bh * 1024 + rowg) * 32 + d0]     + O[m][nt][0] * inv0;
            float o1 = g_v[(bh * 1024 + rowg) * 32 + d0 + 1] + O[m][nt][1] * inv0;
            *(float2*)&g_xv[(b * 1024 + rowg) * 128 + h * 32 + d0] = make_float2(o0, o1);
            float o2 = g_v[(bh * 1024 + rowg + 8) * 32 + d0]     + O[m][nt][2] * inv1;
            float o3 = g_v[(bh * 1024 + rowg + 8) * 32 + d0 + 1] + O[m][nt][3] * inv1;
            *(float2*)&g_xv[(b * 1024 + rowg + 8) * 128 + h * 32 + d0] = make_float2(o2, o3);
        }
    }
}

// ---------------- L7: output proj + residual, transposed store -------------
__global__ __launch_bounds__(256) void k_proj(const float* __restrict__ proj_w, const float* __restrict__ proj_b) {
    __shared__ float As[64 * 65];
    __shared__ __align__(16) float Bs[64 * 66];
    int b = blockIdx.z;
    int n0 = blockIdx.x * 64, j0 = blockIdx.y * 64;
    int tx = threadIdx.x, ty = threadIdx.y, tid = ty * 16 + tx;
    ull s2[4][2];
#pragma unroll
    for (int i = 0; i < 4; i++) { s2[i][0] = 0ull; s2[i][1] = 0ull; }
    for (int kc = 0; kc < 2; kc++) {
        __syncthreads();
        for (int idx = tid; idx < 4096; idx += 256) {
            int r = idx >> 6, kk = idx & 63;
            As[r * 65 + kk] = g_xv[(b * 1024 + n0 + r) * 128 + kc * 64 + kk];
            Bs[kk * 66 + r] = proj_w[(j0 + r) * 128 + kc * 64 + kk];
        }
        __syncthreads();
#pragma unroll 8
        for (int kk = 0; kk < 64; kk++) {
            ull b01 = *(const ull*)&Bs[kk * 66 + ty * 4];
            ull b23 = *(const ull*)&Bs[kk * 66 + ty * 4 + 2];
#pragma unroll
            for (int i = 0; i < 4; i++) {
                ull ad = dup2(As[(i * 16 + tx) * 65 + kk]);
                fma2(s2[i][0], ad, b01);
                fma2(s2[i][1], ad, b23);
            }
        }
    }
#pragma unroll
    for (int i = 0; i < 4; i++)
#pragma unroll
        for (int pr = 0; pr < 2; pr++) {
            float2 f2 = up2(s2[i][pr]);
            int n = n0 + i * 16 + tx;
#pragma unroll
            for (int lane = 0; lane < 2; lane++) {
                int jj = j0 + ty * 4 + pr * 2 + lane;
                float v = (lane ? f2.y : f2.x) + proj_b[jj] + g_ori[(b * 1024 + n) * 128 + jj];
                g_x2[(b * 128 + jj) * 1024 + n] = v;
            }
        }
}

// ---------------- L8: token conv1d via bf16x3 mma + residual ----------------
// Block: (n-tile 128, b). 8 warps; warp w owns n8 tiles {2w,2w+1}, all 8 co m-tiles.
__global__ __launch_bounds__(256, 1) void k_conv1d() {
    __shared__ uint Xph[32 * 136];
    __shared__ uint Xpm[32 * 136];
    int b = blockIdx.y;
    int n0 = blockIdx.x * 128;
    int tid = threadIdx.x;
    int w = tid >> 5, lane = tid & 31, g = lane >> 2, t = lane & 3;

    float acc[2][8][4];
#pragma unroll
    for (int n = 0; n < 2; n++)
#pragma unroll
        for (int m = 0; m < 8; m++)
#pragma unroll
            for (int r = 0; r < 4; r++) acc[n][m][r] = 0.f;

    for (int cc = 0; cc < 2; cc++) {
        __syncthreads();
        for (int it = tid; it < 32 * 132; it += 256) {
            int pr = it / 132, col = it % 132;
            int n = n0 - 2 + col;
            float v0 = 0.f, v1 = 0.f;
            if (n >= 0 && n < 1024) {
                v0 = g_x2[(b * 128 + cc * 64 + 2 * pr) * 1024 + n];
                v1 = g_x2[(b * 128 + cc * 64 + 2 * pr + 1) * 1024 + n];
            }
            ushort h0, m0, h1, m1;
            bsplit(v0, h0, m0); bsplit(v1, h1, m1);
            Xph[pr * 136 + col] = ((uint)h1 << 16) | h0;
            Xpm[pr * 136 + col] = ((uint)m1 << 16) | m0;
        }
        __syncthreads();

        for (int c = 0; c < 20; c++) {
            int kk = c >> 2, cicl = c & 3;
            int gchunk = kk * 8 + cc * 4 + cicl;
            uint bhf[2][2], bmf[2][2];
#pragma unroll
            for (int ntl = 0; ntl < 2; ntl++) {
                int coln = (w * 2 + ntl) * 8 + g + kk;
                int rb = (cicl * 8 + t) * 136 + coln;
                bhf[ntl][0] = Xph[rb];
                bhf[ntl][1] = Xph[rb + 4 * 136];
                bmf[ntl][0] = Xpm[rb];
                bmf[ntl][1] = Xpm[rb + 4 * 136];
            }
#pragma unroll
            for (int mt = 0; mt < 8; mt++) {
                uint4 a4h = *(const uint4*)&g_c1A_h[((gchunk * 8 + mt) * 32 + lane) * 4];
                uint4 a4m = *(const uint4*)&g_c1A_m[((gchunk * 8 + mt) * 32 + lane) * 4];
                uint ah[4] = {a4h.x, a4h.y, a4h.z, a4h.w};
                uint am[4] = {a4m.x, a4m.y, a4m.z, a4m.w};
#pragma unroll
                for (int ntl = 0; ntl < 2; ntl++) {
                    mma_bf16(acc[ntl][mt], ah, bhf[ntl][0], bhf[ntl][1]);
                    mma_bf16(acc[ntl][mt], am, bhf[ntl][0], bhf[ntl][1]);
                    mma_bf16(acc[ntl][mt], ah, bmf[ntl][0], bmf[ntl][1]);
                }
            }
        }
    }

#pragma unroll
    for (int mt = 0; mt < 8; mt++) {
        int coA = mt * 16 + g, coB = coA + 8;
#pragma unroll
        for (int ntl = 0; ntl < 2; ntl++) {
            int n = n0 + (w * 2 + ntl) * 8 + 2 * t;
            float2 rA = *(const float2*)&g_x2[(b * 128 + coA) * 1024 + n];
            *(float2*)&g_y2[(b * 128 + coA) * 1024 + n] =
                make_float2(acc[ntl][mt][0] + rA.x, acc[ntl][mt][1] + rA.y);
            float2 rB = *(const float2*)&g_x2[(b * 128 + coB) * 1024 + n];
            *(float2*)&g_y2[(b * 128 + coB) * 1024 + n] =
                make_float2(acc[ntl][mt][2] + rB.x, acc[ntl][mt][3] + rB.y);
        }
    }
}

// ---------------- L9: bilinear 32->96 upsample (align_corners) -------------
__global__ void k_up(float* __restrict__ out) {
    int j = threadIdx.x;
    int i = blockIdx.x * 4 + threadIdx.y;
    int c = blockIdx.y, b = blockIdx.z;
    const float sc = 31.0f / 95.0f;
    float cy = (float)i * sc;
    int i0 = (int)cy;
    float wy = cy - (float)i0;
    int i1 = min(i0 + 1, 31);
    float cx = (float)j * sc;
    int j0 = (int)cx;
    float wx = cx - (float)j0;
    int j1 = min(j0 + 1, 31);
    const float* Y = &g_y2[(b * 128 + c) * 1024];
    float v00 = Y[i0 * 32 + j0], v10 = Y[i1 * 32 + j0];
    float v01 = Y[i0 * 32 + j1], v11 = Y[i1 * 32 + j1];
    float a0 = v00 * (1.f - wy) + v10 * wy;
    float a1 = v01 * (1.f - wy) + v11 * wy;
    out[((b * 128 + c) * 96 + i) * 96 + j] = a0 * (1.f - wx) + a1 * wx;
}

// ---------------- launch (9 launches; #6 = k_attn gets ncu-profiled) -------
extern "C" void kernel_launch(void* const* d_in, const int* in_sizes, int n_in,
                              void* d_out, int out_size) {
    const float* s1     = (const float*)d_in[0];
    const float* o      = (const float*)d_in[1];
    const int*   index  = (const int*)  d_in[2];
    const float* pe_w   = (const float*)d_in[3];
    const float* bn_g   = (const float*)d_in[4];
    const float* bn_b   = (const float*)d_in[5];
    const float* bn_m   = (const float*)d_in[6];
    const float* bn_v   = (const float*)d_in[7];
    const float* lnx_g  = (const float*)d_in[8];
    const float* lnx_b  = (const float*)d_in[9];
    const float* lny_g  = (const float*)d_in[10];
    const float* lny_b  = (const float*)d_in[11];
    const float* qkv_w  = (const float*)d_in[12];
    const float* qkv_b  = (const float*)d_in[13];
    const float* yv_w   = (const float*)d_in[14];
    const float* yv_b   = (const float*)d_in[15];
    const float* proj_w = (const float*)d_in[16];
    const float* proj_b = (const float*)d_in[17];
    const float* c1d_w  = (const float*)d_in[18];
    float* out = (float*)d_out;

    k_pre       <<<dim3(4, 96, 64), dim3(32, 32)>>>(s1, pe_w, c1d_w);
    k_peconv    <<<dim3(144, 16), 256>>>(index, bn_g, bn_b, bn_m, bn_v);
    k_pool_short<<<dim3(1024, 16), 128>>>(lny_g, lny_b);
    k_pool_o_ln <<<dim3(32, 16), 256>>>(o, lnx_g, lnx_b);
    k_qkv_yv    <<<dim3(16, 8, 16), dim3(16, 16)>>>(qkv_w, qkv_b, yv_w, yv_b);
    k_attn      <<<dim3(8, 64), 128>>>();
    k_proj      <<<dim3(16, 2, 16), dim3(16, 16)>>>(proj_w, proj_b);
    k_conv1d    <<<dim3(8, 16), 256>>>();
    k_up        <<<dim3(24, 128, 16), dim3(96, 4)>>>(out);
}

// round 7
// speedup vs baseline: 1.5502x; 1.0182x over previous
#include <cuda_runtime.h>
#include <cuda_bf16.h>

typedef unsigned long long ull;
typedef unsigned int uint;
typedef unsigned short ushort;

// ---------------- helpers ---------------------------------------------------
__device__ __forceinline__ float ex2(float x) {
    float r; asm("ex2.approx.ftz.f32 %0, %1;" : "=f"(r) : "f"(x)); return r;
}
__device__ __forceinline__ void mma_bf16(float* c, const uint* a, uint b0, uint b1) {
    asm volatile(
        "mma.sync.aligned.m16n8k16.row.col.f32.bf16.bf16.f32 "
        "{%0,%1,%2,%3}, {%4,%5,%6,%7}, {%8,%9}, {%0,%1,%2,%3};"
        : "+f"(c[0]), "+f"(c[1]), "+f"(c[2]), "+f"(c[3])
        : "r"(a[0]), "r"(a[1]), "r"(a[2]), "r"(a[3]), "r"(b0), "r"(b1));
}
__device__ __forceinline__ void bsplit(float v, ushort& h, ushort& m) {
    __nv_bfloat16 bh = __float2bfloat16_rn(v);
    float r = v - __bfloat162float(bh);
    __nv_bfloat16 bm = __float2bfloat16_rn(r);
    h = __bfloat16_as_ushort(bh);
    m = __bfloat16_as_ushort(bm);
}
__device__ __forceinline__ void bsplit2(float a, float b, uint& hi, uint& mi) {
    ushort h0, m0, h1, m1;
    bsplit(a, h0, m0); bsplit(b, h1, m1);
    hi = ((uint)h1 << 16) | h0;
    mi = ((uint)m1 << 16) | m0;
}

// ---------------- scratch (device globals; no allocations) ----------------
__device__ float g_x   [18874368];   // [16][64][18432] patch-major im2col of s1
__device__ float g_z   [18874368];   // conv+bn+relu+mask output
__device__ float g_ori [2097152];    // [16][1024][128] pooled short tokens
__device__ float g_sn  [2097152];    // LN(ori)
__device__ float g_ofr [2097152];    // pooled o tokens (raw)
__device__ float g_of  [2097152];    // LN(of)
__device__ float g_q   [2097152];    // [16][4][1024][32]  (pre-scaled by sc*log2e)
__device__ float g_k   [2097152];
__device__ float g_v   [2097152];
__device__ float g_yv  [2097152];
__device__ float g_xv  [2097152];    // [16][1024][128]
__device__ float g_x2  [2097152];    // [16][128][1024]
__device__ float g_y2  [2097152];    // conv1d output
__device__ uint  g_peA_h[10240],  g_peA_m[10240];    // pe conv A-frags
__device__ uint  g_c1A_h[40960],  g_c1A_m[40960];    // conv1d A-frags
__device__ uint  g_wqA_h[24576],  g_wqA_m[24576];    // qkv_w A-frags (24 mt)
__device__ uint  g_wyA_h[8192],   g_wyA_m[8192];     // yv_w A-frags (8 mt)
__device__ uint  g_wpA_h[8192],   g_wpA_m[8192];     // proj_w A-frags (8 mt)

// ---------------- L1: s1 -> patch-major layout ------------------------------
__global__ void k_transpose(const float* __restrict__ s1) {
    __shared__ float tbuf[32][33];
    int b = blockIdx.z >> 2, cg = blockIdx.z & 3;
    int row = blockIdx.y;
    int W0 = blockIdx.x * 32;
    int tx = threadIdx.x, ty = threadIdx.y;
    tbuf[ty][tx] = s1[((b * 128 + cg * 32 + ty) * 96 + row) * 96 + W0 + tx];
    __syncthreads();
    int Wl = W0 + ty;
    int w = Wl / 12, p2 = Wl % 12;
    int h = row / 12, p1 = row % 12;
    g_x[(b * 64 + h * 8 + w) * 18432 + (p1 * 12 + p2) * 128 + cg * 32 + tx] = tbuf[tx][ty];
}

// ---------------- L2: all weight fragment packs ----------------------------
__global__ void k_wpack(const float* __restrict__ pe_w,
                        const float* __restrict__ c1d_w,
                        const float* __restrict__ qkv_w,
                        const float* __restrict__ yv_w,
                        const float* __restrict__ proj_w) {
    int id = blockIdx.x * 256 + threadIdx.x;
    if (id < 10240) {
        int r = id & 3, lane = (id >> 2) & 31, mt = (id >> 7) & 3, ch = id >> 9;
        int kk = ch >> 2, pc = ch & 3, g = lane >> 2, t = lane & 3;
        int po = mt * 16 + g + 8 * (r & 1);
        int pi0 = pc * 16 + 2 * t + 8 * (r >> 1);
        float w0 = pe_w[(po * 64 + pi0) * 5 + kk];
        float w1 = pe_w[(po * 64 + pi0 + 1) * 5 + kk];
        bsplit2(w0, w1, g_peA_h[id], g_peA_m[id]);
    } else if (id < 51200) {
        int e = id - 10240;
        int r = e & 3, lane = (e >> 2) & 31, mt = (e >> 7) & 7, ch = e >> 10;
        int kk = ch >> 3, cic = ch & 7, g = lane >> 2, t = lane & 3;
        int co = e & 0;  // silence
        co = mt * 16 + g + 8 * (r & 1);
        int ci0 = cic * 16 + 2 * t + 8 * (r >> 1);
        float w0 = c1d_w[(co * 128 + ci0) * 5 + kk];
        float w1 = c1d_w[(co * 128 + ci0 + 1) * 5 + kk];
        bsplit2(w0, w1, g_c1A_h[e], g_c1A_m[e]);
    } else if (id < 75776) {
        int e = id - 51200;
        int r = e & 3, lane = (e >> 2) & 31, cm = e >> 7;
        int mt = cm % 24, kc = cm / 24, g = lane >> 2, t = lane & 3;
        int out = mt * 16 + g + 8 * (r & 1);
        int k = kc * 16 + 2 * t + 8 * (r >> 1);
        bsplit2(qkv_w[out * 128 + k], qkv_w[out * 128 + k + 1], g_wqA_h[e], g_wqA_m[e]);
    } else if (id < 83968) {
        int e = id - 75776;
        int r = e & 3, lane = (e >> 2) & 31, cm = e >> 7;
        int kc = cm >> 3, mt = cm & 7, g = lane >> 2, t = lane & 3;
        int out = mt * 16 + g + 8 * (r & 1);
        int k = kc * 16 + 2 * t + 8 * (r >> 1);
        bsplit2(yv_w[out * 128 + k], yv_w[out * 128 + k + 1], g_wyA_h[e], g_wyA_m[e]);
    } else if (id < 92160) {
        int e = id - 83968;
        int r = e & 3, lane = (e >> 2) & 31, cm = e >> 7;
        int kc = cm >> 3, mt = cm & 7, g = lane >> 2, t = lane & 3;
        int out = mt * 16 + g + 8 * (r & 1);
        int k = kc * 16 + 2 * t + 8 * (r >> 1);
        bsplit2(proj_w[out * 128 + k], proj_w[out * 128 + k + 1], g_wpA_h[e], g_wpA_m[e]);
    }
}

// ---------------- L3: 2x2 pool of o + LN (fused) ---------------------------
__global__ void k_pool_o_ln(const float* __restrict__ o,
                            const float* __restrict__ lnx_g, const float* __restrict__ lnx_b) {
    __shared__ float S[32 * 129];
    int oh = blockIdx.x, b = blockIdx.y;
    int tid = threadIdx.x;
#pragma unroll
    for (int it = 0; it < 16; it++) {
        int idx = it * 256 + tid;
        int c = idx >> 5, ow = idx & 31;
        const float* p = &o[((b * 128 + c) * 64 + 2 * oh) * 64 + 2 * ow];
        S[ow * 129 + c] = 0.25f * (p[0] + p[1] + p[64] + p[65]);
    }
    __syncthreads();
    int warp = tid >> 5, ln = tid & 31;
#pragma unroll
    for (int i = 0; i < 4; i++) {
        int ow = warp * 4 + i;
        float v[4];
        float s = 0.f, s2 = 0.f;
#pragma unroll
        for (int j = 0; j < 4; j++) {
            v[j] = S[ow * 129 + j * 32 + ln];
            s += v[j]; s2 += v[j] * v[j];
        }
#pragma unroll
        for (int off = 16; off; off >>= 1) {
            s  += __shfl_xor_sync(0xffffffffu, s,  off);
            s2 += __shfl_xor_sync(0xffffffffu, s2, off);
        }
        float mean = s * (1.f / 128.f);
        float rstd = rsqrtf(s2 * (1.f / 128.f) - mean * mean + 1e-5f);
        int n = oh * 32 + ow;
#pragma unroll
        for (int j = 0; j < 4; j++) {
            int c = j * 32 + ln;
            g_ofr[(b * 1024 + n) * 128 + c] = v[j];
            g_of [(b * 1024 + n) * 128 + c] = (v[j] - mean) * rstd * lnx_g[c] + lnx_b[c];
        }
    }
}

// ---------------- L4: patch-embed conv (bf16x3) + BN + ReLU + mask ---------
__global__ __launch_bounds__(256) void k_peconv(
    const int* __restrict__ index,
    const float* __restrict__ bn_g, const float* __restrict__ bn_b,
    const float* __restrict__ bn_m, const float* __restrict__ bn_v) {
    __shared__ uint Xph[32 * 136];
    __shared__ uint Xpm[32 * 136];
    int b = blockIdx.y;
    int f0 = blockIdx.x * 128;
    int tid = threadIdx.x;
    int w = tid >> 5, lane = tid & 31, g = lane >> 2, t = lane & 3;

    for (int it = tid; it < 32 * 132; it += 256) {
        int pr = it / 132, col = it % 132;
        int f = f0 - 2 + col;
        float v0 = 0.f, v1 = 0.f;
        if (f >= 0 && f < 18432) {
            v0 = g_x[(b * 64 + 2 * pr) * 18432 + f];
            v1 = g_x[(b * 64 + 2 * pr + 1) * 18432 + f];
        }
        bsplit2(v0, v1, Xph[pr * 136 + col], Xpm[pr * 136 + col]);
    }
    __syncthreads();

    float acc[2][4][4];
#pragma unroll
    for (int n = 0; n < 2; n++)
#pragma unroll
        for (int m = 0; m < 4; m++)
#pragma unroll
            for (int r = 0; r < 4; r++) acc[n][m][r] = 0.f;

    for (int c = 0; c < 20; c++) {
        int kk = c >> 2, pc = c & 3;
        uint bh[2][2], bm[2][2];
#pragma unroll
        for (int ntl = 0; ntl < 2; ntl++) {
            int coln = (w * 2 + ntl) * 8 + g + kk;
            int rb = (pc * 8 + t) * 136 + coln;
            bh[ntl][0] = Xph[rb];
            bh[ntl][1] = Xph[rb + 4 * 136];
            bm[ntl][0] = Xpm[rb];
            bm[ntl][1] = Xpm[rb + 4 * 136];
        }
#pragma unroll
        for (int mt = 0; mt < 4; mt++) {
            uint4 a4h = *(const uint4*)&g_peA_h[((c * 4 + mt) * 32 + lane) * 4];
            uint4 a4m = *(const uint4*)&g_peA_m[((c * 4 + mt) * 32 + lane) * 4];
            uint ah[4] = {a4h.x, a4h.y, a4h.z, a4h.w};
            uint am[4] = {a4m.x, a4m.y, a4m.z, a4m.w};
#pragma unroll
            for (int ntl = 0; ntl < 2; ntl++) {
                mma_bf16(acc[ntl][mt], ah, bh[ntl][0], bh[ntl][1]);
                mma_bf16(acc[ntl][mt], am, bh[ntl][0], bh[ntl][1]);
                mma_bf16(acc[ntl][mt], ah, bm[ntl][0], bm[ntl][1]);
            }
        }
    }

    int pidx0 = (index[0] / 12) * 8 + index[1] / 12;
    int pidx1 = (index[2] / 12) * 8 + index[3] / 12;
    int pidx2 = (index[4] / 12) * 8 + index[5] / 12;
    int pidx3 = (index[6] / 12) * 8 + index[7] / 12;

#pragma unroll
    for (int mt = 0; mt < 4; mt++) {
        int poA = mt * 16 + g, poB = poA + 8;
        bool selA = (poA == pidx0) | (poA == pidx1) | (poA == pidx2) | (poA == pidx3);
        bool selB = (poB == pidx0) | (poB == pidx1) | (poB == pidx2) | (poB == pidx3);
        float mA = bn_m[poA], sA = rsqrtf(bn_v[poA] + 1e-5f), gA = bn_g[poA], bA = bn_b[poA];
        float mB = bn_m[poB], sB = rsqrtf(bn_v[poB] + 1e-5f), gB = bn_g[poB], bB = bn_b[poB];
#pragma unroll
        for (int ntl = 0; ntl < 2; ntl++) {
            int f = f0 + (w * 2 + ntl) * 8 + 2 * t;
            float v0 = fmaxf((acc[ntl][mt][0] - mA) * sA * gA + bA, 0.f);
            float v1 = fmaxf((acc[ntl][mt][1] - mA) * sA * gA + bA, 0.f);
            if (!selA) { v0 *= v0; v1 *= v1; }
            *(float2*)&g_z[(b * 64 + poA) * 18432 + f] = make_float2(v0, v1);
            float v2 = fmaxf((acc[ntl][mt][2] - mB) * sB * gB + bB, 0.f);
            float v3 = fmaxf((acc[ntl][mt][3] - mB) * sB * gB + bB, 0.f);
            if (!selB) { v2 *= v2; v3 *= v3; }
            *(float2*)&g_z[(b * 64 + poB) * 18432 + f] = make_float2(v2, v3);
        }
    }
}

// ---------------- LN helper (blockDim.x == 128) ----------------------------
__device__ __forceinline__ void ln_stats128(float v, float& mean, float& rstd) {
    float s = v, s2 = v * v;
#pragma unroll
    for (int off = 16; off; off >>= 1) {
        s  += __shfl_xor_sync(0xffffffffu, s,  off);
        s2 += __shfl_xor_sync(0xffffffffu, s2, off);
    }
    __shared__ float sm[4], sm2[4];
    int w = threadIdx.x >> 5, ln = threadIdx.x & 31;
    if (ln == 0) { sm[w] = s; sm2[w] = s2; }
    __syncthreads();
    s  = sm[0] + sm[1] + sm[2] + sm[3];
    s2 = sm2[0] + sm2[1] + sm2[2] + sm2[3];
    mean = s * (1.f / 128.f);
    float var = s2 * (1.f / 128.f) - mean * mean;
    rstd = rsqrtf(var + 1e-5f);
}

// ---------------- L5: 3x3 pool of z -> ori + LN -> sn ----------------------
__global__ void k_pool_short(const float* __restrict__ lny_g, const float* __restrict__ lny_b) {
    int n = blockIdx.x, b = blockIdx.y, c = threadIdx.x;
    int oh = n >> 5, ow = n & 31;
    int p = (oh >> 2) * 8 + (ow >> 2);
    int base = (b * 64 + p) * 18432;
    int p1s = (oh & 3) * 3, p2s = (ow & 3) * 3;
    float s = 0.f;
#pragma unroll
    for (int r = 0; r < 3; r++)
#pragma unroll
        for (int t = 0; t < 3; t++)
            s += g_z[base + ((p1s + r) * 12 + p2s + t) * 128 + c];
    s *= (1.f / 9.f);
    g_ori[(b * 1024 + n) * 128 + c] = s;
    float mean, rstd;
    ln_stats128(s, mean, rstd);
    g_sn[(b * 1024 + n) * 128 + c] = (s - mean) * rstd * lny_g[c] + lny_b[c];
}

// ---------------- L6: fused QKV + YV projections (bf16x3 mma) --------------
__global__ __launch_bounds__(256) void k_qkv_yv(const float* __restrict__ qkv_b,
                                                const float* __restrict__ yv_b) {
    __shared__ uint Bph[64 * 72], Bpm[64 * 72];
    int b = blockIdx.z, n0 = blockIdx.x * 64;
    int y = blockIdx.y;
    const float* SRC = y ? g_sn : g_of;
    int tid = threadIdx.x;
    int w = tid >> 5, lane = tid & 31, g = lane >> 2, t = lane & 3;

    for (int i = tid; i < 4096; i += 256) {
        int tok = i >> 6, kp = i & 63;
        float2 v = *(const float2*)&SRC[(b * 1024 + n0 + tok) * 128 + 2 * kp];
        bsplit2(v.x, v.y, Bph[kp * 72 + tok], Bpm[kp * 72 + tok]);
    }
    __syncthreads();

    int MT = y ? 8 : 24;
    const uint* Ah = y ? g_wyA_h : g_wqA_h;
    const uint* Am = y ? g_wyA_m : g_wqA_m;
    const float* bias = y ? yv_b : qkv_b;
    const float qs = 0.17677669529663687f * 1.4426950408889634f;
    int colbase = w * 8 + g;

    for (int mtg = 0; mtg < MT / 4; mtg++) {
        float acc[4][4];
#pragma unroll
        for (int mi = 0; mi < 4; mi++)
#pragma unroll
            for (int r = 0; r < 4; r++) acc[mi][r] = 0.f;
#pragma unroll
        for (int kc = 0; kc < 8; kc++) {
            uint b0h = Bph[(kc * 8 + t) * 72 + colbase];
            uint b1h = Bph[(kc * 8 + t + 4) * 72 + colbase];
            uint b0m = Bpm[(kc * 8 + t) * 72 + colbase];
            uint b1m = Bpm[(kc * 8 + t + 4) * 72 + colbase];
#pragma unroll
            for (int mi = 0; mi < 4; mi++) {
                int mt = mtg * 4 + mi;
                uint4 a4h = *(const uint4*)&Ah[((kc * MT + mt) * 32 + lane) * 4];
                uint4 a4m = *(const uint4*)&Am[((kc * MT + mt) * 32 + lane) * 4];
                uint ah[4] = {a4h.x, a4h.y, a4h.z, a4h.w};
                uint am[4] = {a4m.x, a4m.y, a4m.z, a4m.w};
                mma_bf16(acc[mi], ah, b0h, b1h);
                mma_bf16(acc[mi], am, b0h, b1h);
                mma_bf16(acc[mi], ah, b0m, b1m);
            }
        }
#pragma unroll
        for (int mi = 0; mi < 4; mi++) {
            int mt = mtg * 4 + mi;
            int tok = n0 + w * 8 + 2 * t;
#pragma unroll
            for (int half = 0; half < 2; half++) {
                int jj = mt * 16 + g + 8 * half;
                float v0 = acc[mi][half * 2 + 0] + bias[jj];
                float v1 = acc[mi][half * 2 + 1] + bias[jj];
                if (y == 0) {
                    int which = jj >> 7, rem = jj & 127, hh = rem >> 5, d = rem & 31;
                    float* dst = which == 0 ? g_q : (which == 1 ? g_k : g_v);
                    float sc = which == 0 ? qs : 1.f;
                    dst[((b * 4 + hh) * 1024 + tok) * 32 + d]     = v0 * sc;
                    dst[((b * 4 + hh) * 1024 + tok + 1) * 32 + d] = v1 * sc;
                } else {
                    int hh = jj >> 5, d = jj & 31;
                    g_yv[((b * 4 + hh) * 1024 + tok) * 32 + d]     = v0;
                    g_yv[((b * 4 + hh) * 1024 + tok + 1) * 32 + d] = v1;
                }
            }
        }
    }
}

// ---------------- L7: flash attention (bf16x3 mma, P in registers) ---------
__global__ __launch_bounds__(128) void k_attn() {
    __shared__ uint Kph[16 * 40], Kpm[16 * 40];   // [d-pair][key]
    __shared__ uint Vph[16 * 40], Vpm[16 * 40];   // [key-pair][d]
    int bh = blockIdx.y;
    int b = bh >> 2, hd = bh & 3;
    int q0 = blockIdx.x * 128;
    int tid = threadIdx.x;
    int warp = tid >> 5, lane = tid & 31, g = lane >> 2, t = lane & 3;

    // Q fragments (hi/mid), m16k16, chunks kc=0,1 over d=32
    uint qh[2][2][4], qm[2][2][4];
#pragma unroll
    for (int m = 0; m < 2; m++) {
        int rowg = q0 + m * 64 + warp * 16 + g;
#pragma unroll
        for (int kc = 0; kc < 2; kc++) {
            float2 x0 = *(const float2*)&g_q[(bh * 1024 + rowg) * 32 + kc * 16 + 2 * t];
            float2 x1 = *(const float2*)&g_q[(bh * 1024 + rowg + 8) * 32 + kc * 16 + 2 * t];
            float2 x2 = *(const float2*)&g_q[(bh * 1024 + rowg) * 32 + kc * 16 + 2 * t + 8];
            float2 x3 = *(const float2*)&g_q[(bh * 1024 + rowg + 8) * 32 + kc * 16 + 2 * t + 8];
            bsplit2(x0.x, x0.y, qh[m][kc][0], qm[m][kc][0]);
            bsplit2(x1.x, x1.y, qh[m][kc][1], qm[m][kc][1]);
            bsplit2(x2.x, x2.y, qh[m][kc][2], qm[m][kc][2]);
            bsplit2(x3.x, x3.y, qh[m][kc][3], qm[m][kc][3]);
        }
    }

    float O[2][4][4];
#pragma unroll
    for (int m = 0; m < 2; m++)
#pragma unroll
        for (int nt = 0; nt < 4; nt++)
#pragma unroll
            for (int r = 0; r < 4; r++) O[m][nt][r] = 0.f;
    float l[2][2] = {{0.f, 0.f}, {0.f, 0.f}};

    for (int ct = 0; ct < 32; ct++) {
        int kb = ct * 32;
        __syncthreads();
        for (int i = tid; i < 512; i += 128) {
            int key = i >> 4, dp = i & 15;
            float2 v = *(const float2*)&g_k[(bh * 1024 + kb + key) * 32 + 2 * dp];
            bsplit2(v.x, v.y, Kph[dp * 40 + key], Kpm[dp * 40 + key]);
        }
        for (int i = tid; i < 512; i += 128) {
            int kp = i >> 5, d = i & 31;
            float v0 = g_yv[(bh * 1024 + kb + 2 * kp) * 32 + d];
            float v1 = g_yv[(bh * 1024 + kb + 2 * kp + 1) * 32 + d];
            bsplit2(v0, v1, Vph[kp * 40 + d], Vpm[kp * 40 + d]);
        }
        __syncthreads();

        // S = Q K^T
        float s[2][4][4];
#pragma unroll
        for (int m = 0; m < 2; m++)
#pragma unroll
            for (int nt = 0; nt < 4; nt++)
#pragma unroll
                for (int r = 0; r < 4; r++) s[m][nt][r] = 0.f;
#pragma unroll
        for (int kc = 0; kc < 2; kc++)
#pragma unroll
            for (int nt = 0; nt < 4; nt++) {
                int col = nt * 8 + g;
                uint b0h = Kph[(kc * 8 + t) * 40 + col];
                uint b1h = Kph[(kc * 8 + t + 4) * 40 + col];
                uint b0m = Kpm[(kc * 8 + t) * 40 + col];
                uint b1m = Kpm[(kc * 8 + t + 4) * 40 + col];
#pragma unroll
                for (int m = 0; m < 2; m++) {
                    mma_bf16(s[m][nt], qh[m][kc], b0h, b1h);
                    mma_bf16(s[m][nt], qm[m][kc], b0h, b1h);
                    mma_bf16(s[m][nt], qh[m][kc], b0m, b1m);
                }
            }

        // P = ex2(S); pack A-frags (hi/mid) directly from accumulators
        uint aph[2][2][4], apm[2][2][4];
#pragma unroll
        for (int m = 0; m < 2; m++)
#pragma unroll
            for (int nt = 0; nt < 4; nt++) {
                float p0 = ex2(s[m][nt][0]);
                float p1 = ex2(s[m][nt][1]);
                float p2 = ex2(s[m][nt][2]);
                float p3 = ex2(s[m][nt][3]);
                l[m][0] += p0 + p1;
                l[m][1] += p2 + p3;
                int kc = nt >> 1, hf = nt & 1;
                bsplit2(p0, p1, aph[m][kc][hf * 2 + 0], apm[m][kc][hf * 2 + 0]);
                bsplit2(p2, p3, aph[m][kc][hf * 2 + 1], apm[m][kc][hf * 2 + 1]);
            }

        // O += P V
#pragma unroll
        for (int kc = 0; kc < 2; kc++)
#pragma unroll
            for (int nt = 0; nt < 4; nt++) {
                int col = nt * 8 + g;
                uint b0h = Vph[(kc * 8 + t) * 40 + col];
                uint b1h = Vph[(kc * 8 + t + 4) * 40 + col];
                uint b0m = Vpm[(kc * 8 + t) * 40 + col];
                uint b1m = Vpm[(kc * 8 + t + 4) * 40 + col];
#pragma unroll
                for (int m = 0; m < 2; m++) {
                    mma_bf16(O[m][nt], aph[m][kc], b0h, b1h);
                    mma_bf16(O[m][nt], apm[m][kc], b0h, b1h);
                    mma_bf16(O[m][nt], aph[m][kc], b0m, b1m);
                }
            }
    }

#pragma unroll
    for (int m = 0; m < 2; m++)
#pragma unroll
        for (int r = 0; r < 2; r++) {
            l[m][r] += __shfl_xor_sync(0xffffffffu, l[m][r], 1);
            l[m][r] += __shfl_xor_sync(0xffffffffu, l[m][r], 2);
        }
#pragma unroll
    for (int m = 0; m < 2; m++) {
        int rowg = q0 + m * 64 + warp * 16 + g;
        float inv0 = 1.f / l[m][0];
        float inv1 = 1.f / l[m][1];
#pragma unroll
        for (int nt = 0; nt < 4; nt++) {
            int d0 = nt * 8 + 2 * t;
            float o0 = g_v[(bh * 1024 + rowg) * 32 + d0]     + O[m][nt][0] * inv0;
            float o1 = g_v[(bh * 1024 + rowg) * 32 + d0 + 1] + O[m][nt][1] * inv0;
            *(float2*)&g_xv[(b * 1024 + rowg) * 128 + hd * 32 + d0] = make_float2(o0, o1);
            float o2 = g_v[(bh * 1024 + rowg + 8) * 32 + d0]     + O[m][nt][2] * inv1;
            float o3 = g_v[(bh * 1024 + rowg + 8) * 32 + d0 + 1] + O[m][nt][3] * inv1;
            *(float2*)&g_xv[(b * 1024 + rowg + 8) * 128 + hd * 32 + d0] = make_float2(o2, o3);
        }
    }
}

// ---------------- L8: output proj + residual (bf16x3 mma) ------------------
__global__ __launch_bounds__(256) void k_proj(const float* __restrict__ proj_b) {
    __shared__ uint Bph[64 * 72], Bpm[64 * 72];
    int b = blockIdx.y, n0 = blockIdx.x * 64;
    int tid = threadIdx.x;
    int w = tid >> 5, lane = tid & 31, g = lane >> 2, t = lane & 3;

    for (int i = tid; i < 4096; i += 256) {
        int tok = i >> 6, kp = i & 63;
        float2 v = *(const float2*)&g_xv[(b * 1024 + n0 + tok) * 128 + 2 * kp];
        bsplit2(v.x, v.y, Bph[kp * 72 + tok], Bpm[kp * 72 + tok]);
    }
    __syncthreads();
    int colbase = w * 8 + g;

    for (int mtg = 0; mtg < 2; mtg++) {
        float acc[4][4];
#pragma unroll
        for (int mi = 0; mi < 4; mi++)
#pragma unroll
            for (int r = 0; r < 4; r++) acc[mi][r] = 0.f;
#pragma unroll
        for (int kc = 0; kc < 8; kc++) {
            uint b0h = Bph[(kc * 8 + t) * 72 + colbase];
            uint b1h = Bph[(kc * 8 + t + 4) * 72 + colbase];
            uint b0m = Bpm[(kc * 8 + t) * 72 + colbase];
            uint b1m = Bpm[(kc * 8 + t + 4) * 72 + colbase];
#pragma unroll
            for (int mi = 0; mi < 4; mi++) {
                int mt = mtg * 4 + mi;
                uint4 a4h = *(const uint4*)&g_wpA_h[((kc * 8 + mt) * 32 + lane) * 4];
                uint4 a4m = *(const uint4*)&g_wpA_m[((kc * 8 + mt) * 32 + lane) * 4];
                uint ah[4] = {a4h.x, a4h.y, a4h.z, a4h.w};
                uint am[4] = {a4m.x, a4m.y, a4m.z, a4m.w};
                mma_bf16(acc[mi], ah, b0h, b1h);
                mma_bf16(acc[mi], am, b0h, b1h);
                mma_bf16(acc[mi], ah, b0m, b1m);
            }
        }
#pragma unroll
        for (int mi = 0; mi < 4; mi++) {
            int mt = mtg * 4 + mi;
            int tok = n0 + w * 8 + 2 * t;
#pragma unroll
            for (int half = 0; half < 2; half++) {
                int jj = mt * 16 + g + 8 * half;
                float v0 = acc[mi][half * 2 + 0] + proj_b[jj] + g_ori[(b * 1024 + tok) * 128 + jj];
                float v1 = acc[mi][half * 2 + 1] + proj_b[jj] + g_ori[(b * 1024 + tok + 1) * 128 + jj];
                g_x2[(b * 128 + jj) * 1024 + tok]     = v0;
                g_x2[(b * 128 + jj) * 1024 + tok + 1] = v1;
            }
        }
    }
}

// ---------------- L9: token conv1d (bf16x3 mma) + residual -----------------
__global__ __launch_bounds__(256, 1) void k_conv1d() {
    __shared__ uint Xph[32 * 136];
    __shared__ uint Xpm[32 * 136];
    int b = blockIdx.y;
    int n0 = blockIdx.x * 128;
    int tid = threadIdx.x;
    int w = tid >> 5, lane = tid & 31, g = lane >> 2, t = lane & 3;

    float acc[2][8][4];
#pragma unroll
    for (int n = 0; n < 2; n++)
#pragma unroll
        for (int m = 0; m < 8; m++)
#pragma unroll
            for (int r = 0; r < 4; r++) acc[n][m][r] = 0.f;

    for (int cc = 0; cc < 2; cc++) {
        __syncthreads();
        for (int it = tid; it < 32 * 132; it += 256) {
            int pr = it / 132, col = it % 132;
            int n = n0 - 2 + col;
            float v0 = 0.f, v1 = 0.f;
            if (n >= 0 && n < 1024) {
                v0 = g_x2[(b * 128 + cc * 64 + 2 * pr) * 1024 + n];
                v1 = g_x2[(b * 128 + cc * 64 + 2 * pr + 1) * 1024 + n];
            }
            bsplit2(v0, v1, Xph[pr * 136 + col], Xpm[pr * 136 + col]);
        }
        __syncthreads();

        for (int c = 0; c < 20; c++) {
            int kk = c >> 2, cicl = c & 3;
            int gchunk = kk * 8 + cc * 4 + cicl;
            uint bhf[2][2], bmf[2][2];
#pragma unroll
            for (int ntl = 0; ntl < 2; ntl++) {
                int coln = (w * 2 + ntl) * 8 + g + kk;
                int rb = (cicl * 8 + t) * 136 + coln;
                bhf[ntl][0] = Xph[rb];
                bhf[ntl][1] = Xph[rb + 4 * 136];
                bmf[ntl][0] = Xpm[rb];
                bmf[ntl][1] = Xpm[rb + 4 * 136];
            }
#pragma unroll
            for (int mt = 0; mt < 8; mt++) {
                uint4 a4h = *(const uint4*)&g_c1A_h[((gchunk * 8 + mt) * 32 + lane) * 4];
                uint4 a4m = *(const uint4*)&g_c1A_m[((gchunk * 8 + mt) * 32 + lane) * 4];
                uint ah[4] = {a4h.x, a4h.y, a4h.z, a4h.w};
                uint am[4] = {a4m.x, a4m.y, a4m.z, a4m.w};
#pragma unroll
                for (int ntl = 0; ntl < 2; ntl++) {
                    mma_bf16(acc[ntl][mt], ah, bhf[ntl][0], bhf[ntl][1]);
                    mma_bf16(acc[ntl][mt], am, bhf[ntl][0], bhf[ntl][1]);
                    mma_bf16(acc[ntl][mt], ah, bmf[ntl][0], bmf[ntl][1]);
                }
            }
        }
    }

#pragma unroll
    for (int mt = 0; mt < 8; mt++) {
        int coA = mt * 16 + g, coB = coA + 8;
#pragma unroll
        for (int ntl = 0; ntl < 2; ntl++) {
            int n = n0 + (w * 2 + ntl) * 8 + 2 * t;
            float2 rA = *(const float2*)&g_x2[(b * 128 + coA) * 1024 + n];
            *(float2*)&g_y2[(b * 128 + coA) * 1024 + n] =
                make_float2(acc[ntl][mt][0] + rA.x, acc[ntl][mt][1] + rA.y);
            float2 rB = *(const float2*)&g_x2[(b * 128 + coB) * 1024 + n];
            *(float2*)&g_y2[(b * 128 + coB) * 1024 + n] =
                make_float2(acc[ntl][mt][2] + rB.x, acc[ntl][mt][3] + rB.y);
        }
    }
}

// ---------------- L10: bilinear 32->96 upsample ----------------------------
__global__ void k_up(float* __restrict__ out) {
    int j = threadIdx.x;
    int i = blockIdx.x * 4 + threadIdx.y;
    int c = blockIdx.y, b = blockIdx.z;
    const float sc = 31.0f / 95.0f;
    float cy = (float)i * sc;
    int i0 = (int)cy;
    float wy = cy - (float)i0;
    int i1 = min(i0 + 1, 31);
    float cx = (float)j * sc;
    int j0 = (int)cx;
    float wx = cx - (float)j0;
    int j1 = min(j0 + 1, 31);
    const float* Y = &g_y2[(b * 128 + c) * 1024];
    float v00 = Y[i0 * 32 + j0], v10 = Y[i1 * 32 + j0];
    float v01 = Y[i0 * 32 + j1], v11 = Y[i1 * 32 + j1];
    float a0 = v00 * (1.f - wy) + v10 * wy;
    float a1 = v01 * (1.f - wy) + v11 * wy;
    out[((b * 128 + c) * 96 + i) * 96 + j] = a0 * (1.f - wx) + a1 * wx;
}

// ---------------- launch (k_peconv at slot 4 -> gets ncu-profiled) ---------
extern "C" void kernel_launch(void* const* d_in, const int* in_sizes, int n_in,
                              void* d_out, int out_size) {
    const float* s1     = (const float*)d_in[0];
    const float* o      = (const float*)d_in[1];
    const int*   index  = (const int*)  d_in[2];
    const float* pe_w   = (const float*)d_in[3];
    const float* bn_g   = (const float*)d_in[4];
    const float* bn_b   = (const float*)d_in[5];
    const float* bn_m   = (const float*)d_in[6];
    const float* bn_v   = (const float*)d_in[7];
    const float* lnx_g  = (const float*)d_in[8];
    const float* lnx_b  = (const float*)d_in[9];
    const float* lny_g  = (const float*)d_in[10];
    const float* lny_b  = (const float*)d_in[11];
    const float* qkv_w  = (const float*)d_in[12];
    const float* qkv_b  = (const float*)d_in[13];
    const float* yv_w   = (const float*)d_in[14];
    const float* yv_b   = (const float*)d_in[15];
    const float* proj_w = (const float*)d_in[16];
    const float* proj_b = (const float*)d_in[17];
    const float* c1d_w  = (const float*)d_in[18];
    float* out = (float*)d_out;

    k_transpose <<<dim3(3, 96, 64), dim3(32, 32)>>>(s1);
    k_wpack     <<<360, 256>>>(pe_w, c1d_w, qkv_w, yv_w, proj_w);
    k_pool_o_ln <<<dim3(32, 16), 256>>>(o, lnx_g, lnx_b);
    k_peconv    <<<dim3(144, 16), 256>>>(index, bn_g, bn_b, bn_m, bn_v);
    k_pool_short<<<dim3(1024, 16), 128>>>(lny_g, lny_b);
    k_qkv_yv    <<<dim3(16, 2, 16), 256>>>(qkv_b, yv_b);
    k_attn      <<<dim3(8, 64), 128>>>();
    k_proj      <<<dim3(16, 16), 256>>>(proj_b);
    k_conv1d    <<<dim3(8, 16), 256>>>();
    k_up        <<<dim3(24, 128, 16), dim3(96, 4)>>>(out);
}

// round 10
// speedup vs baseline: 1.8082x; 1.1664x over previous
#include <cuda_runtime.h>
#include <cuda_bf16.h>

typedef unsigned long long ull;
typedef unsigned int uint;
typedef unsigned short ushort;

// ---------------- helpers ---------------------------------------------------
__device__ __forceinline__ float ex2(float x) {
    float r; asm("ex2.approx.ftz.f32 %0, %1;" : "=f"(r) : "f"(x)); return r;
}
__device__ __forceinline__ void mma_bf16(float* c, const uint* a, uint b0, uint b1) {
    asm volatile(
        "mma.sync.aligned.m16n8k16.row.col.f32.bf16.bf16.f32 "
        "{%0,%1,%2,%3}, {%4,%5,%6,%7}, {%8,%9}, {%0,%1,%2,%3};"
        : "+f"(c[0]), "+f"(c[1]), "+f"(c[2]), "+f"(c[3])
        : "r"(a[0]), "r"(a[1]), "r"(a[2]), "r"(a[3]), "r"(b0), "r"(b1));
}
__device__ __forceinline__ void bsplit(float v, ushort& h, ushort& m) {
    __nv_bfloat16 bh = __float2bfloat16_rn(v);
    float r = v - __bfloat162float(bh);
    __nv_bfloat16 bm = __float2bfloat16_rn(r);
    h = __bfloat16_as_ushort(bh);
    m = __bfloat16_as_ushort(bm);
}
__device__ __forceinline__ void bsplit2(float a, float b, uint& hi, uint& mi) {
    ushort h0, m0, h1, m1;
    bsplit(a, h0, m0); bsplit(b, h1, m1);
    hi = ((uint)h1 << 16) | h0;
    mi = ((uint)m1 << 16) | m0;
}

// ---------------- scratch (device globals; no allocations) ----------------
__device__ float g_x   [18874368];
__device__ float g_z   [18874368];
__device__ float g_ori [2097152];
__device__ float g_sn  [2097152];
__device__ float g_ofr [2097152];
__device__ float g_of  [2097152];
__device__ float g_q   [2097152];
__device__ float g_k   [2097152];
__device__ float g_v   [2097152];
__device__ float g_yv  [2097152];
__device__ float g_xv  [2097152];
__device__ float g_x2  [2097152];
__device__ float g_y2  [2097152];
__device__ uint  g_peA_h[10240],  g_peA_m[10240];
__device__ uint  g_c1A_h[40960],  g_c1A_m[40960];
__device__ uint  g_wqA_h[24576],  g_wqA_m[24576];
__device__ uint  g_wyA_h[8192],   g_wyA_m[8192];
__device__ uint  g_wpA_h[8192],   g_wpA_m[8192];

// ---------------- L1: s1 -> patch-major layout ------------------------------
__global__ void k_transpose(const float* __restrict__ s1) {
    __shared__ float tbuf[32][33];
    int b = blockIdx.z >> 2, cg = blockIdx.z & 3;
    int row = blockIdx.y;
    int W0 = blockIdx.x * 32;
    int tx = threadIdx.x, ty = threadIdx.y;
    tbuf[ty][tx] = s1[((b * 128 + cg * 32 + ty) * 96 + row) * 96 + W0 + tx];
    __syncthreads();
    int Wl = W0 + ty;
    int w = Wl / 12, p2 = Wl % 12;
    int h = row / 12, p1 = row % 12;
    g_x[(b * 64 + h * 8 + w) * 18432 + (p1 * 12 + p2) * 128 + cg * 32 + tx] = tbuf[tx][ty];
}

// ---------------- L2: all weight fragment packs ----------------------------
__global__ void k_wpack(const float* __restrict__ pe_w,
                        const float* __restrict__ c1d_w,
                        const float* __restrict__ qkv_w,
                        const float* __restrict__ yv_w,
                        const float* __restrict__ proj_w) {
    int id = blockIdx.x * 256 + threadIdx.x;
    if (id < 10240) {
        int r = id & 3, lane = (id >> 2) & 31, mt = (id >> 7) & 3, ch = id >> 9;
        int kk = ch >> 2, pc = ch & 3, g = lane >> 2, t = lane & 3;
        int po = mt * 16 + g + 8 * (r & 1);
        int pi0 = pc * 16 + 2 * t + 8 * (r >> 1);
        float w0 = pe_w[(po * 64 + pi0) * 5 + kk];
        float w1 = pe_w[(po * 64 + pi0 + 1) * 5 + kk];
        bsplit2(w0, w1, g_peA_h[id], g_peA_m[id]);
    } else if (id < 51200) {
        int e = id - 10240;
        int r = e & 3, lane = (e >> 2) & 31, mt = (e >> 7) & 7, ch = e >> 10;
        int kk = ch >> 3, cic = ch & 7, g = lane >> 2, t = lane & 3;
        int co = mt * 16 + g + 8 * (r & 1);
        int ci0 = cic * 16 + 2 * t + 8 * (r >> 1);
        float w0 = c1d_w[(co * 128 + ci0) * 5 + kk];
        float w1 = c1d_w[(co * 128 + ci0 + 1) * 5 + kk];
        bsplit2(w0, w1, g_c1A_h[e], g_c1A_m[e]);
    } else if (id < 75776) {
        int e = id - 51200;
        int r = e & 3, lane = (e >> 2) & 31, cm = e >> 7;
        int mt = cm % 24, kc = cm / 24, g = lane >> 2, t = lane & 3;
        int out = mt * 16 + g + 8 * (r & 1);
        int k = kc * 16 + 2 * t + 8 * (r >> 1);
        bsplit2(qkv_w[out * 128 + k], qkv_w[out * 128 + k + 1], g_wqA_h[e], g_wqA_m[e]);
    } else if (id < 83968) {
        int e = id - 75776;
        int r = e & 3, lane = (e >> 2) & 31, cm = e >> 7;
        int kc = cm >> 3, mt = cm & 7, g = lane >> 2, t = lane & 3;
        int out = mt * 16 + g + 8 * (r & 1);
        int k = kc * 16 + 2 * t + 8 * (r >> 1);
        bsplit2(yv_w[out * 128 + k], yv_w[out * 128 + k + 1], g_wyA_h[e], g_wyA_m[e]);
    } else if (id < 92160) {
        int e = id - 83968;
        int r = e & 3, lane = (e >> 2) & 31, cm = e >> 7;
        int kc = cm >> 3, mt = cm & 7, g = lane >> 2, t = lane & 3;
        int out = mt * 16 + g + 8 * (r & 1);
        int k = kc * 16 + 2 * t + 8 * (r >> 1);
        bsplit2(proj_w[out * 128 + k], proj_w[out * 128 + k + 1], g_wpA_h[e], g_wpA_m[e]);
    }
}

// ---------------- L3: 2x2 pool of o + LN (fused) ---------------------------
__global__ void k_pool_o_ln(const float* __restrict__ o,
                            const float* __restrict__ lnx_g, const float* __restrict__ lnx_b) {
    __shared__ float S[32 * 129];
    int oh = blockIdx.x, b = blockIdx.y;
    int tid = threadIdx.x;
#pragma unroll
    for (int it = 0; it < 16; it++) {
        int idx = it * 256 + tid;
        int c = idx >> 5, ow = idx & 31;
        const float* p = &o[((b * 128 + c) * 64 + 2 * oh) * 64 + 2 * ow];
        S[ow * 129 + c] = 0.25f * (p[0] + p[1] + p[64] + p[65]);
    }
    __syncthreads();
    int warp = tid >> 5, ln = tid & 31;
#pragma unroll
    for (int i = 0; i < 4; i++) {
        int ow = warp * 4 + i;
        float v[4];
        float s = 0.f, s2 = 0.f;
#pragma unroll
        for (int j = 0; j < 4; j++) {
            v[j] = S[ow * 129 + j * 32 + ln];
            s += v[j]; s2 += v[j] * v[j];
        }
#pragma unroll
        for (int off = 16; off; off >>= 1) {
            s  += __shfl_xor_sync(0xffffffffu, s,  off);
            s2 += __shfl_xor_sync(0xffffffffu, s2, off);
        }
        float mean = s * (1.f / 128.f);
        float rstd = rsqrtf(s2 * (1.f / 128.f) - mean * mean + 1e-5f);
        int n = oh * 32 + ow;
#pragma unroll
        for (int j = 0; j < 4; j++) {
            int c = j * 32 + ln;
            g_ofr[(b * 1024 + n) * 128 + c] = v[j];
            g_of [(b * 1024 + n) * 128 + c] = (v[j] - mean) * rstd * lnx_g[c] + lnx_b[c];
        }
    }
}

// ---------------- L4: patch-embed conv (bf16x3, A-prefetch) ----------------
__global__ __launch_bounds__(256) void k_peconv(
    const int* __restrict__ index,
    const float* __restrict__ bn_g, const float* __restrict__ bn_b,
    const float* __restrict__ bn_m, const float* __restrict__ bn_v) {
    __shared__ uint Xph[32 * 136];
    __shared__ uint Xpm[32 * 136];
    int b = blockIdx.y;
    int f0 = blockIdx.x * 128;
    int tid = threadIdx.x;
    int w = tid >> 5, lane = tid & 31, g = lane >> 2, t = lane & 3;

    for (int it = tid; it < 32 * 132; it += 256) {
        int pr = it / 132, col = it % 132;
        int f = f0 - 2 + col;
        float v0 = 0.f, v1 = 0.f;
        if (f >= 0 && f < 18432) {
            v0 = g_x[(b * 64 + 2 * pr) * 18432 + f];
            v1 = g_x[(b * 64 + 2 * pr + 1) * 18432 + f];
        }
        bsplit2(v0, v1, Xph[pr * 136 + col], Xpm[pr * 136 + col]);
    }
    __syncthreads();

    float acc[2][4][4];
#pragma unroll
    for (int n = 0; n < 2; n++)
#pragma unroll
        for (int m = 0; m < 4; m++)
#pragma unroll
            for (int r = 0; r < 4; r++) acc[n][m][r] = 0.f;

    uint4 cah[4], cam[4], nah[4], nam[4];
#pragma unroll
    for (int mt = 0; mt < 4; mt++) {
        cah[mt] = *(const uint4*)&g_peA_h[(mt * 32 + lane) * 4];
        cam[mt] = *(const uint4*)&g_peA_m[(mt * 32 + lane) * 4];
    }

    for (int c = 0; c < 20; c++) {
        int kk = c >> 2, pc = c & 3;
        uint bh[2][2], bm[2][2];
#pragma unroll
        for (int ntl = 0; ntl < 2; ntl++) {
            int coln = (w * 2 + ntl) * 8 + g + kk;
            int rb = (pc * 8 + t) * 136 + coln;
            bh[ntl][0] = Xph[rb];
            bh[ntl][1] = Xph[rb + 4 * 136];
            bm[ntl][0] = Xpm[rb];
            bm[ntl][1] = Xpm[rb + 4 * 136];
        }
        if (c < 19) {
#pragma unroll
            for (int mt = 0; mt < 4; mt++) {
                nah[mt] = *(const uint4*)&g_peA_h[(((c + 1) * 4 + mt) * 32 + lane) * 4];
                nam[mt] = *(const uint4*)&g_peA_m[(((c + 1) * 4 + mt) * 32 + lane) * 4];
            }
        }
#pragma unroll
        for (int mt = 0; mt < 4; mt++) {
            uint ah[4] = {cah[mt].x, cah[mt].y, cah[mt].z, cah[mt].w};
            uint am[4] = {cam[mt].x, cam[mt].y, cam[mt].z, cam[mt].w};
#pragma unroll
            for (int ntl = 0; ntl < 2; ntl++) {
                mma_bf16(acc[ntl][mt], ah, bh[ntl][0], bh[ntl][1]);
                mma_bf16(acc[ntl][mt], am, bh[ntl][0], bh[ntl][1]);
                mma_bf16(acc[ntl][mt], ah, bm[ntl][0], bm[ntl][1]);
            }
        }
        if (c < 19) {
#pragma unroll
            for (int mt = 0; mt < 4; mt++) { cah[mt] = nah[mt]; cam[mt] = nam[mt]; }
        }
    }

    int pidx0 = (index[0] / 12) * 8 + index[1] / 12;
    int pidx1 = (index[2] / 12) * 8 + index[3] / 12;
    int pidx2 = (index[4] / 12) * 8 + index[5] / 12;
    int pidx3 = (index[6] / 12) * 8 + index[7] / 12;

#pragma unroll
    for (int mt = 0; mt < 4; mt++) {
        int poA = mt * 16 + g, poB = poA + 8;
        bool selA = (poA == pidx0) | (poA == pidx1) | (poA == pidx2) | (poA == pidx3);
        bool selB = (poB == pidx0) | (poB == pidx1) | (poB == pidx2) | (poB == pidx3);
        float mA = bn_m[poA], sA = rsqrtf(bn_v[poA] + 1e-5f), gA = bn_g[poA], bA = bn_b[poA];
        float mB = bn_m[poB], sB = rsqrtf(bn_v[poB] + 1e-5f), gB = bn_g[poB], bB = bn_b[poB];
#pragma unroll
        for (int ntl = 0; ntl < 2; ntl++) {
            int f = f0 + (w * 2 + ntl) * 8 + 2 * t;
            float v0 = fmaxf((acc[ntl][mt][0] - mA) * sA * gA + bA, 0.f);
            float v1 = fmaxf((acc[ntl][mt][1] - mA) * sA * gA + bA, 0.f);
            if (!selA) { v0 *= v0; v1 *= v1; }
            *(float2*)&g_z[(b * 64 + poA) * 18432 + f] = make_float2(v0, v1);
            float v2 = fmaxf((acc[ntl][mt][2] - mB) * sB * gB + bB, 0.f);
            float v3 = fmaxf((acc[ntl][mt][3] - mB) * sB * gB + bB, 0.f);
            if (!selB) { v2 *= v2; v3 *= v3; }
            *(float2*)&g_z[(b * 64 + poB) * 18432 + f] = make_float2(v2, v3);
        }
    }
}

// ---------------- LN helper (blockDim.x == 128) ----------------------------
__device__ __forceinline__ void ln_stats128(float v, float& mean, float& rstd) {
    float s = v, s2 = v * v;
#pragma unroll
    for (int off = 16; off; off >>= 1) {
        s  += __shfl_xor_sync(0xffffffffu, s,  off);
        s2 += __shfl_xor_sync(0xffffffffu, s2, off);
    }
    __shared__ float sm[4], sm2[4];
    int w = threadIdx.x >> 5, ln = threadIdx.x & 31;
    if (ln == 0) { sm[w] = s; sm2[w] = s2; }
    __syncthreads();
    s  = sm[0] + sm[1] + sm[2] + sm[3];
    s2 = sm2[0] + sm2[1] + sm2[2] + sm2[3];
    mean = s * (1.f / 128.f);
    float var = s2 * (1.f / 128.f) - mean * mean;
    rstd = rsqrtf(var + 1e-5f);
}

// ---------------- L5: 3x3 pool of z -> ori + LN -> sn ----------------------
__global__ void k_pool_short(const float* __restrict__ lny_g, const float* __restrict__ lny_b) {
    int n = blockIdx.x, b = blockIdx.y, c = threadIdx.x;
    int oh = n >> 5, ow = n & 31;
    int p = (oh >> 2) * 8 + (ow >> 2);
    int base = (b * 64 + p) * 18432;
    int p1s = (oh & 3) * 3, p2s = (ow & 3) * 3;
    float s = 0.f;
#pragma unroll
    for (int r = 0; r < 3; r++)
#pragma unroll
        for (int t = 0; t < 3; t++)
            s += g_z[base + ((p1s + r) * 12 + p2s + t) * 128 + c];
    s *= (1.f / 9.f);
    g_ori[(b * 1024 + n) * 128 + c] = s;
    float mean, rstd;
    ln_stats128(s, mean, rstd);
    g_sn[(b * 1024 + n) * 128 + c] = (s - mean) * rstd * lny_g[c] + lny_b[c];
}

// ---------------- L6: fused QKV + YV projections (bf16x3 mma) --------------
__global__ __launch_bounds__(256) void k_qkv_yv(const float* __restrict__ qkv_b,
                                                const float* __restrict__ yv_b) {
    __shared__ uint Bph[64 * 72], Bpm[64 * 72];
    int b = blockIdx.z, n0 = blockIdx.x * 64;
    int y = blockIdx.y;
    const float* SRC = y ? g_sn : g_of;
    int tid = threadIdx.x;
    int w = tid >> 5, lane = tid & 31, g = lane >> 2, t = lane & 3;

    for (int i = tid; i < 4096; i += 256) {
        int tok = i >> 6, kp = i & 63;
        float2 v = *(const float2*)&SRC[(b * 1024 + n0 + tok) * 128 + 2 * kp];
        bsplit2(v.x, v.y, Bph[kp * 72 + tok], Bpm[kp * 72 + tok]);
    }
    __syncthreads();

    int MT = y ? 8 : 24;
    const uint* Ah = y ? g_wyA_h : g_wqA_h;
    const uint* Am = y ? g_wyA_m : g_wqA_m;
    const float* bias = y ? yv_b : qkv_b;
    const float qs = 0.17677669529663687f * 1.4426950408889634f;
    int colbase = w * 8 + g;

    for (int mtg = 0; mtg < MT / 4; mtg++) {
        float acc[4][4];
#pragma unroll
        for (int mi = 0; mi < 4; mi++)
#pragma unroll
            for (int r = 0; r < 4; r++) acc[mi][r] = 0.f;
#pragma unroll
        for (int kc = 0; kc < 8; kc++) {
            uint b0h = Bph[(kc * 8 + t) * 72 + colbase];
            uint b1h = Bph[(kc * 8 + t + 4) * 72 + colbase];
            uint b0m = Bpm[(kc * 8 + t) * 72 + colbase];
            uint b1m = Bpm[(kc * 8 + t + 4) * 72 + colbase];
#pragma unroll
            for (int mi = 0; mi < 4; mi++) {
                int mt = mtg * 4 + mi;
                uint4 a4h = *(const uint4*)&Ah[((kc * MT + mt) * 32 + lane) * 4];
                uint4 a4m = *(const uint4*)&Am[((kc * MT + mt) * 32 + lane) * 4];
                uint ah[4] = {a4h.x, a4h.y, a4h.z, a4h.w};
                uint am[4] = {a4m.x, a4m.y, a4m.z, a4m.w};
                mma_bf16(acc[mi], ah, b0h, b1h);
                mma_bf16(acc[mi], am, b0h, b1h);
                mma_bf16(acc[mi], ah, b0m, b1m);
            }
        }
#pragma unroll
        for (int mi = 0; mi < 4; mi++) {
            int mt = mtg * 4 + mi;
            int tok = n0 + w * 8 + 2 * t;
#pragma unroll
            for (int half = 0; half < 2; half++) {
                int jj = mt * 16 + g + 8 * half;
                float v0 = acc[mi][half * 2 + 0] + bias[jj];
                float v1 = acc[mi][half * 2 + 1] + bias[jj];
                if (y == 0) {
                    int which = jj >> 7, rem = jj & 127, hh = rem >> 5, d = rem & 31;
                    float* dst = which == 0 ? g_q : (which == 1 ? g_k : g_v);
                    float sc = which == 0 ? qs : 1.f;
                    dst[((b * 4 + hh) * 1024 + tok) * 32 + d]     = v0 * sc;
                    dst[((b * 4 + hh) * 1024 + tok + 1) * 32 + d] = v1 * sc;
                } else {
                    int hh = jj >> 5, d = jj & 31;
                    g_yv[((b * 4 + hh) * 1024 + tok) * 32 + d]     = v0;
                    g_yv[((b * 4 + hh) * 1024 + tok + 1) * 32 + d] = v1;
                }
            }
        }
    }
}

// ---------------- L7: flash attention (bf16x3 mma, KV double-buffer) -------
__global__ __launch_bounds__(128) void k_attn() {
    __shared__ uint Kph[16 * 40], Kpm[16 * 40];
    __shared__ uint Vph[16 * 40], Vpm[16 * 40];
    int bh = blockIdx.y;
    int b = bh >> 2, hd = bh & 3;
    int q0 = blockIdx.x * 128;
    int tid = threadIdx.x;
    int warp = tid >> 5, lane = tid & 31, g = lane >> 2, t = lane & 3;

    uint qh[2][2][4], qm[2][2][4];
#pragma unroll
    for (int m = 0; m < 2; m++) {
        int rowg = q0 + m * 64 + warp * 16 + g;
#pragma unroll
        for (int kc = 0; kc < 2; kc++) {
            float2 x0 = *(const float2*)&g_q[(bh * 1024 + rowg) * 32 + kc * 16 + 2 * t];
            float2 x1 = *(const float2*)&g_q[(bh * 1024 + rowg + 8) * 32 + kc * 16 + 2 * t];
            float2 x2 = *(const float2*)&g_q[(bh * 1024 + rowg) * 32 + kc * 16 + 2 * t + 8];
            float2 x3 = *(const float2*)&g_q[(bh * 1024 + rowg + 8) * 32 + kc * 16 + 2 * t + 8];
            bsplit2(x0.x, x0.y, qh[m][kc][0], qm[m][kc][0]);
            bsplit2(x1.x, x1.y, qh[m][kc][1], qm[m][kc][1]);
            bsplit2(x2.x, x2.y, qh[m][kc][2], qm[m][kc][2]);
            bsplit2(x3.x, x3.y, qh[m][kc][3], qm[m][kc][3]);
        }
    }

    float O[2][4][4];
#pragma unroll
    for (int m = 0; m < 2; m++)
#pragma unroll
        for (int nt = 0; nt < 4; nt++)
#pragma unroll
            for (int r = 0; r < 4; r++) O[m][nt][r] = 0.f;
    float l[2][2] = {{0.f, 0.f}, {0.f, 0.f}};

    float2 kreg[4];
    float vreg0[4], vreg1[4];
#define LOAD_KV(CT) do {                                                          \
        int kb_ = (CT) * 32;                                                      \
        _Pragma("unroll")                                                         \
        for (int ii = 0; ii < 4; ii++) {                                          \
            int i_ = ii * 128 + tid;                                              \
            int key_ = i_ >> 4, dp_ = i_ & 15;                                    \
            kreg[ii] = *(const float2*)&g_k[(bh * 1024 + kb_ + key_) * 32 + 2 * dp_]; \
            int kp_ = i_ >> 5, d_ = i_ & 31;                                      \
            vreg0[ii] = g_yv[(bh * 1024 + kb_ + 2 * kp_) * 32 + d_];              \
            vreg1[ii] = g_yv[(bh * 1024 + kb_ + 2 * kp_ + 1) * 32 + d_];          \
        }                                                                         \
    } while (0)

    LOAD_KV(0);

    for (int ct = 0; ct < 32; ct++) {
        // write staged registers to smem (bf16 split)
#pragma unroll
        for (int ii = 0; ii < 4; ii++) {
            int i_ = ii * 128 + tid;
            int key_ = i_ >> 4, dp_ = i_ & 15;
            bsplit2(kreg[ii].x, kreg[ii].y, Kph[dp_ * 40 + key_], Kpm[dp_ * 40 + key_]);
            int kp_ = i_ >> 5, d_ = i_ & 31;
            bsplit2(vreg0[ii], vreg1[ii], Vph[kp_ * 40 + d_], Vpm[kp_ * 40 + d_]);
        }
        __syncthreads();
        if (ct < 31) LOAD_KV(ct + 1);   // in flight under compute

        // S = Q K^T
        float s[2][4][4];
#pragma unroll
        for (int m = 0; m < 2; m++)
#pragma unroll
            for (int nt = 0; nt < 4; nt++)
#pragma unroll
                for (int r = 0; r < 4; r++) s[m][nt][r] = 0.f;
#pragma unroll
        for (int kc = 0; kc < 2; kc++)
#pragma unroll
            for (int nt = 0; nt < 4; nt++) {
                int col = nt * 8 + g;
                uint b0h = Kph[(kc * 8 + t) * 40 + col];
                uint b1h = Kph[(kc * 8 + t + 4) * 40 + col];
                uint b0m = Kpm[(kc * 8 + t) * 40 + col];
                uint b1m = Kpm[(kc * 8 + t + 4) * 40 + col];
#pragma unroll
                for (int m = 0; m < 2; m++) {
                    mma_bf16(s[m][nt], qh[m][kc], b0h, b1h);
                    mma_bf16(s[m][nt], qm[m][kc], b0h, b1h);
                    mma_bf16(s[m][nt], qh[m][kc], b0m, b1m);
                }
            }

        // P = ex2(S); pack A-frags directly from accumulators
        uint aph[2][2][4], apm[2][2][4];
#pragma unroll
        for (int m = 0; m < 2; m++)
#pragma unroll
            for (int nt = 0; nt < 4; nt++) {
                float p0 = ex2(s[m][nt][0]);
                float p1 = ex2(s[m][nt][1]);
                float p2 = ex2(s[m][nt][2]);
                float p3 = ex2(s[m][nt][3]);
                l[m][0] += p0 + p1;
                l[m][1] += p2 + p3;
                int kc = nt >> 1, hf = nt & 1;
                bsplit2(p0, p1, aph[m][kc][hf * 2 + 0], apm[m][kc][hf * 2 + 0]);
                bsplit2(p2, p3, aph[m][kc][hf * 2 + 1], apm[m][kc][hf * 2 + 1]);
            }

        // O += P V
#pragma unroll
        for (int kc = 0; kc < 2; kc++)
#pragma unroll
            for (int nt = 0; nt < 4; nt++) {
                int col = nt * 8 + g;
                uint b0h = Vph[(kc * 8 + t) * 40 + col];
                uint b1h = Vph[(kc * 8 + t + 4) * 40 + col];
                uint b0m = Vpm[(kc * 8 + t) * 40 + col];
                uint b1m = Vpm[(kc * 8 + t + 4) * 40 + col];
#pragma unroll
                for (int m = 0; m < 2; m++) {
                    mma_bf16(O[m][nt], aph[m][kc], b0h, b1h);
                    mma_bf16(O[m][nt], apm[m][kc], b0h, b1h);
                    mma_bf16(O[m][nt], aph[m][kc], b0m, b1m);
                }
            }
        __syncthreads();
    }
#undef LOAD_KV

#pragma unroll
    for (int m = 0; m < 2; m++)
#pragma unroll
        for (int r = 0; r < 2; r++) {
            l[m][r] += __shfl_xor_sync(0xffffffffu, l[m][r], 1);
            l[m][r] += __shfl_xor_sync(0xffffffffu, l[m][r], 2);
        }
#pragma unroll
    for (int m = 0; m < 2; m++) {
        int rowg = q0 + m * 64 + warp * 16 + g;
        float inv0 = 1.f / l[m][0];
        float inv1 = 1.f / l[m][1];
#pragma unroll
        for (int nt = 0; nt < 4; nt++) {
            int d0 = nt * 8 + 2 * t;
            float o0 = g_v[(bh * 1024 + rowg) * 32 + d0]     + O[m][nt][0] * inv0;
            float o1 = g_v[(bh * 1024 + rowg) * 32 + d0 + 1] + O[m][nt][1] * inv0;
            *(float2*)&g_xv[(b * 1024 + rowg) * 128 + hd * 32 + d0] = make_float2(o0, o1);
            float o2 = g_v[(bh * 1024 + rowg + 8) * 32 + d0]     + O[m][nt][2] * inv1;
            float o3 = g_v[(bh * 1024 + rowg + 8) * 32 + d0 + 1] + O[m][nt][3] * inv1;
            *(float2*)&g_xv[(b * 1024 + rowg + 8) * 128 + hd * 32 + d0] = make_float2(o2, o3);
        }
    }
}

// ---------------- L8: output proj + residual (bf16x3 mma) ------------------
__global__ __launch_bounds__(256) void k_proj(const float* __restrict__ proj_b) {
    __shared__ uint Bph[64 * 72], Bpm[64 * 72];
    int b = blockIdx.y, n0 = blockIdx.x * 64;
    int tid = threadIdx.x;
    int w = tid >> 5, lane = tid & 31, g = lane >> 2, t = lane & 3;

    for (int i = tid; i < 4096; i += 256) {
        int tok = i >> 6, kp = i & 63;
        float2 v = *(const float2*)&g_xv[(b * 1024 + n0 + tok) * 128 + 2 * kp];
        bsplit2(v.x, v.y, Bph[kp * 72 + tok], Bpm[kp * 72 + tok]);
    }
    __syncthreads();
    int colbase = w * 8 + g;

    for (int mtg = 0; mtg < 2; mtg++) {
        float acc[4][4];
#pragma unroll
        for (int mi = 0; mi < 4; mi++)
#pragma unroll
            for (int r = 0; r < 4; r++) acc[mi][r] = 0.f;
#pragma unroll
        for (int kc = 0; kc < 8; kc++) {
            uint b0h = Bph[(kc * 8 + t) * 72 + colbase];
            uint b1h = Bph[(kc * 8 + t + 4) * 72 + colbase];
            uint b0m = Bpm[(kc * 8 + t) * 72 + colbase];
            uint b1m = Bpm[(kc * 8 + t + 4) * 72 + colbase];
#pragma unroll
            for (int mi = 0; mi < 4; mi++) {
                int mt = mtg * 4 + mi;
                uint4 a4h = *(const uint4*)&g_wpA_h[((kc * 8 + mt) * 32 + lane) * 4];
                uint4 a4m = *(const uint4*)&g_wpA_m[((kc * 8 + mt) * 32 + lane) * 4];
                uint ah[4] = {a4h.x, a4h.y, a4h.z, a4h.w};
                uint am[4] = {a4m.x, a4m.y, a4m.z, a4m.w};
                mma_bf16(acc[mi], ah, b0h, b1h);
                mma_bf16(acc[mi], am, b0h, b1h);
                mma_bf16(acc[mi], ah, b0m, b1m);
            }
        }
#pragma unroll
        for (int mi = 0; mi < 4; mi++) {
            int mt = mtg * 4 + mi;
            int tok = n0 + w * 8 + 2 * t;
#pragma unroll
            for (int half = 0; half < 2; half++) {
                int jj = mt * 16 + g + 8 * half;
                float v0 = acc[mi][half * 2 + 0] + proj_b[jj] + g_ori[(b * 1024 + tok) * 128 + jj];
                float v1 = acc[mi][half * 2 + 1] + proj_b[jj] + g_ori[(b * 1024 + tok + 1) * 128 + jj];
                g_x2[(b * 128 + jj) * 1024 + tok]     = v0;
                g_x2[(b * 128 + jj) * 1024 + tok + 1] = v1;
            }
        }
    }
}

// ---------------- L9: token conv1d (bf16x3, n-tile 64, A-prefetch) ---------
__global__ __launch_bounds__(256) void k_conv1d() {
    __shared__ uint Xph[32 * 72];
    __shared__ uint Xpm[32 * 72];
    int b = blockIdx.y;
    int n0 = blockIdx.x * 64;
    int tid = threadIdx.x;
    int w = tid >> 5, lane = tid & 31, g = lane >> 2, t = lane & 3;

    float acc[8][4];
#pragma unroll
    for (int m = 0; m < 8; m++)
#pragma unroll
        for (int r = 0; r < 4; r++) acc[m][r] = 0.f;

    for (int cc = 0; cc < 2; cc++) {
        __syncthreads();
        for (int it = tid; it < 32 * 68; it += 256) {
            int pr = it / 68, col = it % 68;
            int n = n0 - 2 + col;
            float v0 = 0.f, v1 = 0.f;
            if (n >= 0 && n < 1024) {
                v0 = g_x2[(b * 128 + cc * 64 + 2 * pr) * 1024 + n];
                v1 = g_x2[(b * 128 + cc * 64 + 2 * pr + 1) * 1024 + n];
            }
            bsplit2(v0, v1, Xph[pr * 72 + col], Xpm[pr * 72 + col]);
        }
        __syncthreads();

        for (int mtg = 0; mtg < 2; mtg++) {
            uint4 cah[4], cam[4], nah[4], nam[4];
            {
                int gchunk0 = cc * 4;      // c=0 -> kk=0, cicl=0
#pragma unroll
                for (int mi = 0; mi < 4; mi++) {
                    int mt = mtg * 4 + mi;
                    cah[mi] = *(const uint4*)&g_c1A_h[((gchunk0 * 8 + mt) * 32 + lane) * 4];
                    cam[mi] = *(const uint4*)&g_c1A_m[((gchunk0 * 8 + mt) * 32 + lane) * 4];
                }
            }
            for (int c = 0; c < 20; c++) {
                int kk = c >> 2, cicl = c & 3;
                int coln = w * 8 + g + kk;
                int rb = (cicl * 8 + t) * 72 + coln;
                uint b0h = Xph[rb];
                uint b1h = Xph[rb + 4 * 72];
                uint b0m = Xpm[rb];
                uint b1m = Xpm[rb + 4 * 72];
                if (c < 19) {
                    int c1 = c + 1;
                    int gch = (c1 >> 2) * 8 + cc * 4 + (c1 & 3);
#pragma unroll
                    for (int mi = 0; mi < 4; mi++) {
                        int mt = mtg * 4 + mi;
                        nah[mi] = *(const uint4*)&g_c1A_h[((gch * 8 + mt) * 32 + lane) * 4];
                        nam[mi] = *(const uint4*)&g_c1A_m[((gch * 8 + mt) * 32 + lane) * 4];
                    }
                }
#pragma unroll
                for (int mi = 0; mi < 4; mi++) {
                    uint ah[4] = {cah[mi].x, cah[mi].y, cah[mi].z, cah[mi].w};
                    uint am[4] = {cam[mi].x, cam[mi].y, cam[mi].z, cam[mi].w};
                    mma_bf16(acc[mtg * 4 + mi], ah, b0h, b1h);
                    mma_bf16(acc[mtg * 4 + mi], am, b0h, b1h);
                    mma_bf16(acc[mtg * 4 + mi], ah, b0m, b1m);
                }
                if (c < 19) {
#pragma unroll
                    for (int mi = 0; mi < 4; mi++) { cah[mi] = nah[mi]; cam[mi] = nam[mi]; }
                }
            }
        }
    }

#pragma unroll
    for (int mt = 0; mt < 8; mt++) {
        int coA = mt * 16 + g, coB = coA + 8;
        int n = n0 + w * 8 + 2 * t;
        float2 rA = *(const float2*)&g_x2[(b * 128 + coA) * 1024 + n];
        *(float2*)&g_y2[(b * 128 + coA) * 1024 + n] =
            make_float2(acc[mt][0] + rA.x, acc[mt][1] + rA.y);
        float2 rB = *(const float2*)&g_x2[(b * 128 + coB) * 1024 + n];
        *(float2*)&g_y2[(b * 128 + coB) * 1024 + n] =
            make_float2(acc[mt][2] + rB.x, acc[mt][3] + rB.y);
    }
}

// ---------------- L10: bilinear 32->96 upsample ----------------------------
__global__ void k_up(float* __restrict__ out) {
    int j = threadIdx.x;
    int i = blockIdx.x * 4 + threadIdx.y;
    int c = blockIdx.y, b = blockIdx.z;
    const float sc = 31.0f / 95.0f;
    float cy = (float)i * sc;
    int i0 = (int)cy;
    float wy = cy - (float)i0;
    int i1 = min(i0 + 1, 31);
    float cx = (float)j * sc;
    int j0 = (int)cx;
    float wx = cx - (float)j0;
    int j1 = min(j0 + 1, 31);
    const float* Y = &g_y2[(b * 128 + c) * 1024];
    float v00 = Y[i0 * 32 + j0], v10 = Y[i1 * 32 + j0];
    float v01 = Y[i0 * 32 + j1], v11 = Y[i1 * 32 + j1];
    float a0 = v00 * (1.f - wy) + v10 * wy;
    float a1 = v01 * (1.f - wy) + v11 * wy;
    out[((b * 128 + c) * 96 + i) * 96 + j] = a0 * (1.f - wx) + a1 * wx;
}

// ---------------- launch (k_peconv stays at profiled slot 4) ---------------
extern "C" void kernel_launch(void* const* d_in, const int* in_sizes, int n_in,
                              void* d_out, int out_size) {
    const float* s1     = (const float*)d_in[0];
    const float* o      = (const float*)d_in[1];
    const int*   index  = (const int*)  d_in[2];
    const float* pe_w   = (const float*)d_in[3];
    const float* bn_g   = (const float*)d_in[4];
    const float* bn_b   = (const float*)d_in[5];
    const float* bn_m   = (const float*)d_in[6];
    const float* bn_v   = (const float*)d_in[7];
    const float* lnx_g  = (const float*)d_in[8];
    const float* lnx_b  = (const float*)d_in[9];
    const float* lny_g  = (const float*)d_in[10];
    const float* lny_b  = (const float*)d_in[11];
    const float* qkv_b  = (const float*)d_in[13];
    const float* yv_b   = (const float*)d_in[15];
    const float* proj_b = (const float*)d_in[17];
    const float* qkv_w  = (const float*)d_in[12];
    const float* yv_w   = (const float*)d_in[14];
    const float* proj_w = (const float*)d_in[16];
    const float* c1d_w  = (const float*)d_in[18];
    float* out = (float*)d_out;

    k_transpose <<<dim3(3, 96, 64), dim3(32, 32)>>>(s1);
    k_wpack     <<<360, 256>>>(pe_w, c1d_w, qkv_w, yv_w, proj_w);
    k_pool_o_ln <<<dim3(32, 16), 256>>>(o, lnx_g, lnx_b);
    k_peconv    <<<dim3(144, 16), 256>>>(index, bn_g, bn_b, bn_m, bn_v);
    k_pool_short<<<dim3(1024, 16), 128>>>(lny_g, lny_b);
    k_qkv_yv    <<<dim3(16, 2, 16), 256>>>(qkv_b, yv_b);
    k_attn      <<<dim3(8, 64), 128>>>();
    k_proj      <<<dim3(16, 16), 256>>>(proj_b);
    k_conv1d    <<<dim3(16, 16), 256>>>();
    k_up        <<<dim3(24, 128, 16), dim3(96, 4)>>>(out);
}